// round 14
// baseline (speedup 1.0000x reference)
#include <cuda_runtime.h>
#include <cuda_bf16.h>
#include <cstdint>

// Problem constants (fixed by the dataset)
#define NN 50000
#define EE 800000
#define GG 64
#define HH 128
#define OO 10
#define PPB 8   // pooling partials per graph
#define SCB 256 // scan block size
#define SH  4   // CSR atomic shards per node

// ---------------- static device scratch ----------------
__device__ float g_bufA[NN * HH];
__device__ float g_bufB[NN * HH];
__device__ float g_R[NN * HH];     // h @ W_root^T + b
__device__ int   g_count[NN * SH + 1];
__device__ int   g_rowptr[NN + 1];
__device__ int   g_cursor[NN * SH];
__device__ int   g_col[EE];
__device__ int   g_bsum[(NN * SH + SCB - 1) / SCB + 1];
__device__ int   g_boff[(NN * SH + SCB - 1) / SCB + 1];
__device__ int   g_gstart[GG + 1];
__device__ float g_inv[GG];
__device__ float g_pmax8[GG * PPB * HH];
__device__ float g_psum8[GG * PPB * HH];
__device__ float g_emb[GG * 2 * HH];
__device__ int   g_idx64;
// bf16 hi/lo split buffers
__device__ __nv_bfloat16 g_xH[NN * HH],   g_xL[NN * HH];    // x splits (gemmR1 input)
__device__ __nv_bfloat16 g_aggH[NN * HH], g_aggL[NN * HH];  // AGG splits (gemm_rel input)
__device__ __nv_bfloat16 g_hAH[NN * HH],  g_hAL[NN * HH];   // h1 splits
__device__ __nv_bfloat16 g_hBH[NN * HH],  g_hBL[NN * HH];   // h2 splits
__device__ __nv_bfloat16 g_wH[6 * HH * HH], g_wL[6 * HH * HH];

// ---------------- small helpers ----------------
__device__ __forceinline__ uint32_t pack_bf16(float a, float b) {
    __nv_bfloat162 t = __floats2bfloat162_rn(a, b);
    return *(uint32_t*)&t;
}
__device__ __forceinline__ void ldsm4(uint32_t r[4], const void* p) {
    uint32_t a = (uint32_t)__cvta_generic_to_shared(p);
    asm volatile("ldmatrix.sync.aligned.m8n8.x4.shared.b16 {%0,%1,%2,%3}, [%4];"
                 : "=r"(r[0]), "=r"(r[1]), "=r"(r[2]), "=r"(r[3]) : "r"(a));
}
__device__ __forceinline__ void mma_bf16(float c[4], const uint32_t a[4],
                                         uint32_t b0, uint32_t b1) {
    asm volatile("mma.sync.aligned.m16n8k16.row.col.f32.bf16.bf16.f32 "
                 "{%0,%1,%2,%3}, {%4,%5,%6,%7}, {%8,%9}, {%0,%1,%2,%3};"
                 : "+f"(c[0]), "+f"(c[1]), "+f"(c[2]), "+f"(c[3])
                 : "r"(a[0]), "r"(a[1]), "r"(a[2]), "r"(a[3]), "r"(b0), "r"(b1));
}
// swizzled offset of 16B unit u (0..3) in row r (row = 64B of bf16)
__device__ __forceinline__ int swzoff(int r, int u) {
    return r * 64 + (((u ^ ((r >> 1) & 3)) & 3) << 4);
}
__device__ __forceinline__ void cp_async16(void* dst, const void* src, int bytes) {
    uint32_t d = (uint32_t)__cvta_generic_to_shared(dst);
    asm volatile("cp.async.cg.shared.global [%0], [%1], 16, %2;"
                 :: "r"(d), "l"(src), "r"(bytes) : "memory");
}
#define CP_COMMIT() asm volatile("cp.async.commit_group;" ::: "memory")
#define CP_WAIT1()  asm volatile("cp.async.wait_group 1;" ::: "memory")
#define CP_WAIT0()  asm volatile("cp.async.wait_group 0;" ::: "memory")

// ---------------- index dtype handling ----------------
__device__ __forceinline__ int idx_at(const void* p, long long i) {
    if (g_idx64) return (int)((const long long*)p)[i];
    return ((const int*)p)[i];
}

__global__ void detect_idx_kernel(const void* ei, int n) {
    const long long* p = (const long long*)ei;
    int ok = 1;
    for (int i = 0; i < 4; i++) {
        long long v = p[i];
        if (v < 0 || v >= (long long)n) ok = 0;
    }
    g_idx64 = ok;
}

// ---------------- hi/lo bf16 splits ----------------
__global__ void split_kernel(const float* __restrict__ src, __nv_bfloat16* __restrict__ dh,
                             __nv_bfloat16* __restrict__ dl, int count4) {
    int i = blockIdx.x * blockDim.x + threadIdx.x;
    if (i < count4) {
        float4 v = ((const float4*)src)[i];
        uint32_t h01 = pack_bf16(v.x, v.y);
        uint32_t h23 = pack_bf16(v.z, v.w);
        __nv_bfloat162 h0 = *(__nv_bfloat162*)&h01;
        __nv_bfloat162 h1 = *(__nv_bfloat162*)&h23;
        uint32_t l01 = pack_bf16(v.x - __bfloat162float(h0.x), v.y - __bfloat162float(h0.y));
        uint32_t l23 = pack_bf16(v.z - __bfloat162float(h1.x), v.w - __bfloat162float(h1.y));
        ((uint2*)dh)[i] = make_uint2(h01, h23);
        ((uint2*)dl)[i] = make_uint2(l01, l23);
    }
}

__global__ void split6_kernel(const float* w0, const float* w1, const float* w2,
                              const float* w3, const float* w4, const float* w5,
                              __nv_bfloat16* __restrict__ dh, __nv_bfloat16* __restrict__ dl) {
    int i = blockIdx.x * blockDim.x + threadIdx.x;   // over 6*4096
    if (i < 6 * 4096) {
        int m = i >> 12;
        int j = i & 4095;
        const float* src = (m == 0) ? w0 : (m == 1) ? w1 : (m == 2) ? w2
                          : (m == 3) ? w3 : (m == 4) ? w4 : w5;
        float4 v = ((const float4*)src)[j];
        uint32_t h01 = pack_bf16(v.x, v.y);
        uint32_t h23 = pack_bf16(v.z, v.w);
        __nv_bfloat162 h0 = *(__nv_bfloat162*)&h01;
        __nv_bfloat162 h1 = *(__nv_bfloat162*)&h23;
        uint32_t l01 = pack_bf16(v.x - __bfloat162float(h0.x), v.y - __bfloat162float(h0.y));
        uint32_t l23 = pack_bf16(v.z - __bfloat162float(h1.x), v.w - __bfloat162float(h1.y));
        ((uint2*)dh)[i] = make_uint2(h01, h23);
        ((uint2*)dl)[i] = make_uint2(l01, l23);
    }
}

// ---------------- setup kernels ----------------
__global__ void zero_misc_kernel(int nbins) {
    int stride = gridDim.x * blockDim.x;
    int i = blockIdx.x * blockDim.x + threadIdx.x;
    for (int k = i; k < nbins + 1; k += stride) g_count[k] = 0;
    for (int k = i; k < GG * 2 * HH; k += stride) g_emb[k] = 0.f;
}

__global__ void hist_edges_kernel(const void* ei, int E) {
    int e = blockIdx.x * blockDim.x + threadIdx.x;
    if (e < E) {
        int d = idx_at(ei, (long long)E + e);
        atomicAdd(&g_count[d * SH + (e & (SH - 1))], 1);
    }
}

// ---------------- 3-phase parallel scan over nbins = N*SH ----------------
__global__ void scan1_kernel(int nbins) {
    int i = blockIdx.x * SCB + threadIdx.x;
    int v = (i < nbins) ? g_count[i] : 0;
#pragma unroll
    for (int o = 16; o; o >>= 1) v += __shfl_down_sync(0xffffffffu, v, o);
    __shared__ int ws[SCB / 32];
    if ((threadIdx.x & 31) == 0) ws[threadIdx.x >> 5] = v;
    __syncthreads();
    if (threadIdx.x < SCB / 32) {
        int s = ws[threadIdx.x];
#pragma unroll
        for (int o = (SCB / 64); o; o >>= 1) s += __shfl_down_sync(0xffu, s, o);
        if (threadIdx.x == 0) g_bsum[blockIdx.x] = s;
    }
}

__global__ void scan2_kernel(int nb, int N) {
    int t = threadIdx.x;
    int lane = t & 31;
    int wp = t >> 5;
    int orig = (t < nb) ? g_bsum[t] : 0;
    int v = orig;
#pragma unroll
    for (int o = 1; o < 32; o <<= 1) {
        int u = __shfl_up_sync(0xffffffffu, v, o);
        if (lane >= o) v += u;
    }
    __shared__ int ws[32];
    if (lane == 31) ws[wp] = v;
    __syncthreads();
    if (t < 32) {
        int s = ws[t];
#pragma unroll
        for (int o = 1; o < 32; o <<= 1) {
            int u = __shfl_up_sync(0xffffffffu, s, o);
            if (t >= o) s += u;
        }
        ws[t] = s;
    }
    __syncthreads();
    int incl = v + ((wp > 0) ? ws[wp - 1] : 0);
    if (t < nb) g_boff[t] = incl - orig;
    if (t == nb - 1) g_rowptr[N] = incl;
}

__global__ void scan3_kernel(int nbins) {
    int b = blockIdx.x;
    int t = threadIdx.x;
    int i = b * SCB + t;
    int orig = (i < nbins) ? g_count[i] : 0;
    int v = orig;
#pragma unroll
    for (int o = 1; o < 32; o <<= 1) {
        int u = __shfl_up_sync(0xffffffffu, v, o);
        if ((t & 31) >= o) v += u;
    }
    __shared__ int ws[SCB / 32];
    if ((t & 31) == 31) ws[t >> 5] = v;
    __syncthreads();
    if (t < SCB / 32) {
        int s = ws[t];
#pragma unroll
        for (int o = 1; o < SCB / 32; o <<= 1) {
            int u = __shfl_up_sync((1u << (SCB / 32)) - 1u, s, o);
            if (t >= o) s += u;
        }
        ws[t] = s;
    }
    __syncthreads();
    int incl = v + ((t >= 32) ? ws[(t >> 5) - 1] : 0);
    int excl = incl - orig + g_boff[b];
    if (i < nbins) {
        g_cursor[i] = excl;
        if ((i & (SH - 1)) == 0) g_rowptr[i / SH] = excl;
    }
}

__global__ void scatter_kernel(const void* ei, int E) {
    int e = blockIdx.x * blockDim.x + threadIdx.x;
    if (e < E) {
        int d = idx_at(ei, (long long)E + e);
        int s = idx_at(ei, e);
        int pos = atomicAdd(&g_cursor[d * SH + (e & (SH - 1))], 1);
        g_col[pos] = s;
    }
}

// batch is sorted: graph boundaries via binary search
__global__ void gstart_kernel(const void* batch, int n) {
    int g = threadIdx.x;
    if (g <= GG) {
        if (g == GG) {
            g_gstart[GG] = n;
        } else {
            int lo = 0, hi = n;
            while (lo < hi) {
                int mid = (lo + hi) >> 1;
                if (idx_at(batch, mid) < g) lo = mid + 1; else hi = mid;
            }
            g_gstart[g] = lo;
        }
    }
    __syncthreads();
    if (g < GG) {
        int c = g_gstart[g + 1] - g_gstart[g];
        g_inv[g] = 1.0f / (float)max(c, 1);
    }
}

// ---------------- SpMM gather + split ----------------
// AGG[d] = sum_{e: dst==d} Hsrc[src[e]] -> written as bf16 hi/lo pair.
__global__ void __launch_bounds__(256) spmm_split_kernel(
    const float* __restrict__ Hsrc, __nv_bfloat16* __restrict__ AggH,
    __nv_bfloat16* __restrict__ AggL, int n) {
    int w = (blockIdx.x * blockDim.x + threadIdx.x) >> 5;
    int lane = threadIdx.x & 31;
    if (w >= n) return;
    const float4* h4 = (const float4*)Hsrc;
    int s = g_rowptr[w];
    int e = g_rowptr[w + 1];
    float4 a0 = make_float4(0.f, 0.f, 0.f, 0.f);
    float4 a1 = make_float4(0.f, 0.f, 0.f, 0.f);
    float4 a2 = make_float4(0.f, 0.f, 0.f, 0.f);
    float4 a3 = make_float4(0.f, 0.f, 0.f, 0.f);
    int i = s;
    for (; i + 3 < e; i += 4) {
        int c0 = g_col[i + 0];
        int c1 = g_col[i + 1];
        int c2 = g_col[i + 2];
        int c3 = g_col[i + 3];
        float4 v0 = h4[(size_t)c0 * 32 + lane];
        float4 v1 = h4[(size_t)c1 * 32 + lane];
        float4 v2 = h4[(size_t)c2 * 32 + lane];
        float4 v3 = h4[(size_t)c3 * 32 + lane];
        a0.x += v0.x; a0.y += v0.y; a0.z += v0.z; a0.w += v0.w;
        a1.x += v1.x; a1.y += v1.y; a1.z += v1.z; a1.w += v1.w;
        a2.x += v2.x; a2.y += v2.y; a2.z += v2.z; a2.w += v2.w;
        a3.x += v3.x; a3.y += v3.y; a3.z += v3.z; a3.w += v3.w;
    }
    for (; i < e; i++) {
        float4 v = h4[(size_t)g_col[i] * 32 + lane];
        a0.x += v.x; a0.y += v.y; a0.z += v.z; a0.w += v.w;
    }
    float4 r;
    r.x = (a0.x + a1.x) + (a2.x + a3.x);
    r.y = (a0.y + a1.y) + (a2.y + a3.y);
    r.z = (a0.z + a1.z) + (a2.z + a3.z);
    r.w = (a0.w + a1.w) + (a2.w + a3.w);
    uint32_t h01 = pack_bf16(r.x, r.y);
    uint32_t h23 = pack_bf16(r.z, r.w);
    __nv_bfloat162 b0 = *(__nv_bfloat162*)&h01;
    __nv_bfloat162 b1 = *(__nv_bfloat162*)&h23;
    uint32_t l01 = pack_bf16(r.x - __bfloat162float(b0.x), r.y - __bfloat162float(b0.y));
    uint32_t l23 = pack_bf16(r.z - __bfloat162float(b1.x), r.w - __bfloat162float(b1.y));
    ((uint2*)AggH)[(size_t)w * 32 + lane] = make_uint2(h01, h23);
    ((uint2*)AggL)[(size_t)w * 32 + lane] = make_uint2(l01, l23);
}

// ---------------- bf16-split GEMM (K=128): C = A@B^T [+bias] [+Rin] [relu] ----------------
// Optional bf16 hi/lo split output (Ch/Cl) for the next consumer.
#define GEMM_SMEM (2 * 4 * 8192)
__global__ void __launch_bounds__(256) gemm_half_kernel(
    const __nv_bfloat16* __restrict__ Ah, const __nv_bfloat16* __restrict__ Al,
    const __nv_bfloat16* __restrict__ Bh, const __nv_bfloat16* __restrict__ Bl,
    const float* __restrict__ bias, const float* __restrict__ Rin,
    float* __restrict__ C, __nv_bfloat16* __restrict__ Ch, __nv_bfloat16* __restrict__ Cl,
    int n, int doRelu)
{
    extern __shared__ __align__(128) uint8_t sm[];
    int tid = threadIdx.x;
    int lane = tid & 31;
    int wid = tid >> 5;
    int warpM = wid & 3;
    int warpN = wid >> 2;
    int row0 = blockIdx.x * 128;

    float acc[2][8][4];
#pragma unroll
    for (int mf = 0; mf < 2; mf++)
#pragma unroll
        for (int nf = 0; nf < 8; nf++)
#pragma unroll
            for (int q = 0; q < 4; q++) acc[mf][nf][q] = 0.f;

    auto load_chunk = [&](int c, int s) {
        int kb2 = c * 64;
        uint8_t* sA_h = sm + s * 32768;
        uint8_t* sA_l = sA_h + 8192;
        uint8_t* sB_h = sA_h + 16384;
        uint8_t* sB_l = sA_h + 24576;
#pragma unroll
        for (int j = 0; j < 2; j++) {
            int uu = tid * 2 + j;
            int row = uu >> 2;
            int un = uu & 3;
            int sw = swzoff(row, un);
            int grow = row0 + row;
            int ok = (grow < n) ? 16 : 0;
            int gr = (grow < n) ? grow : 0;
            size_t aoff = (size_t)gr * 256 + kb2 + un * 16;
            size_t boff = (size_t)row * 256 + kb2 + un * 16;
            cp_async16(sA_h + sw, (const char*)Ah + aoff, ok);
            cp_async16(sA_l + sw, (const char*)Al + aoff, ok);
            cp_async16(sB_h + sw, (const char*)Bh + boff, 16);
            cp_async16(sB_l + sw, (const char*)Bl + boff, 16);
        }
    };

    load_chunk(0, 0);
    CP_COMMIT();

    for (int c = 0; c < 4; c++) {
        int s = c & 1;
        if (c + 1 < 4) {
            load_chunk(c + 1, s ^ 1);
            CP_COMMIT();
            CP_WAIT1();
        } else {
            CP_WAIT0();
        }
        __syncthreads();
        uint8_t* sA_h = sm + s * 32768;
        uint8_t* sA_l = sA_h + 8192;
        uint8_t* sB_h = sA_h + 16384;
        uint8_t* sB_l = sA_h + 24576;
#pragma unroll
        for (int st = 0; st < 2; st++) {
            uint32_t ah[2][4], al[2][4];
            int arow = warpM * 32 + (lane & 15);
            int au = 2 * st + (lane >> 4);
#pragma unroll
            for (int mf = 0; mf < 2; mf++) {
                ldsm4(ah[mf], sA_h + swzoff(arow + mf * 16, au));
                ldsm4(al[mf], sA_l + swzoff(arow + mf * 16, au));
            }
            int brow_off = (lane & 7) + ((lane >> 4) << 3);
            int bu = 2 * st + ((lane >> 3) & 1);
#pragma unroll
            for (int nf2 = 0; nf2 < 4; nf2++) {
                int brow = warpN * 64 + nf2 * 16 + brow_off;
                uint32_t bh[4], bl[4];
                ldsm4(bh, sB_h + swzoff(brow, bu));
                ldsm4(bl, sB_l + swzoff(brow, bu));
#pragma unroll
                for (int half = 0; half < 2; half++) {
                    int nf = nf2 * 2 + half;
#pragma unroll
                    for (int mf = 0; mf < 2; mf++) {
                        mma_bf16(acc[mf][nf], ah[mf], bh[half * 2], bh[half * 2 + 1]);
                        mma_bf16(acc[mf][nf], ah[mf], bl[half * 2], bl[half * 2 + 1]);
                        mma_bf16(acc[mf][nf], al[mf], bh[half * 2], bh[half * 2 + 1]);
                    }
                }
            }
        }
        __syncthreads();
    }
    // ---- epilogue: [+bias] [+Rin] [relu], fp32 out, optional bf16 split out ----
#pragma unroll
    for (int mf = 0; mf < 2; mf++) {
        int row_lo = row0 + warpM * 32 + mf * 16 + (lane >> 2);
#pragma unroll
        for (int nf = 0; nf < 8; nf++) {
            int col = warpN * 64 + nf * 8 + (lane & 3) * 2;
            float b0 = bias ? bias[col] : 0.f;
            float b1 = bias ? bias[col + 1] : 0.f;
#pragma unroll
            for (int hw = 0; hw < 2; hw++) {
                int row = row_lo + hw * 8;
                if (row < n) {
                    float2 o;
                    o.x = acc[mf][nf][hw * 2 + 0] + b0;
                    o.y = acc[mf][nf][hw * 2 + 1] + b1;
                    if (Rin) {
                        float2 rv = *(const float2*)&Rin[(size_t)row * 128 + col];
                        o.x += rv.x;
                        o.y += rv.y;
                    }
                    if (doRelu) {
                        o.x = fmaxf(o.x, 0.f);
                        o.y = fmaxf(o.y, 0.f);
                    }
                    *(float2*)&C[(size_t)row * 128 + col] = o;
                    if (Ch) {
                        uint32_t ph = pack_bf16(o.x, o.y);
                        __nv_bfloat162 hb = *(__nv_bfloat162*)&ph;
                        uint32_t pl = pack_bf16(o.x - __bfloat162float(hb.x),
                                                o.y - __bfloat162float(hb.y));
                        ((uint32_t*)Ch)[(size_t)row * 64 + (col >> 1)] = ph;
                        ((uint32_t*)Cl)[(size_t)row * 64 + (col >> 1)] = pl;
                    }
                }
            }
        }
    }
}

// ---------------- pooling ----------------
__global__ void pool_kernel(const float* __restrict__ h) {
    int g = blockIdx.x / PPB;
    int p = blockIdx.x % PPB;
    int t = threadIdx.x;
    int n0 = g_gstart[g];
    int n1 = g_gstart[g + 1];
    int cnt = n1 - n0;
    int chunk = (cnt + PPB - 1) / PPB;
    int i0 = n0 + p * chunk;
    int i1 = min(i0 + chunk, n1);
    float mx0 = 0.f, mx1 = 0.f, sm0 = 0.f, sm1 = 0.f;
    int i = i0;
    for (; i + 1 < i1; i += 2) {
        float v0 = h[(size_t)i * HH + t];
        float v1 = h[(size_t)(i + 1) * HH + t];
        mx0 = fmaxf(mx0, v0);
        mx1 = fmaxf(mx1, v1);
        sm0 += v0;
        sm1 += v1;
    }
    if (i < i1) {
        float v = h[(size_t)i * HH + t];
        mx0 = fmaxf(mx0, v);
        sm0 += v;
    }
    g_pmax8[(g * PPB + p) * HH + t] = fmaxf(mx0, mx1);
    g_psum8[(g * PPB + p) * HH + t] = sm0 + sm1;
}

__global__ void pool_accum_kernel() {
    int idx = blockIdx.x * blockDim.x + threadIdx.x;
    if (idx < GG * HH) {
        int g = idx >> 7;
        int f = idx & 127;
        float mx = 0.f, sm = 0.f;
#pragma unroll
        for (int p = 0; p < PPB; p++) {
            mx = fmaxf(mx, g_pmax8[(g * PPB + p) * HH + f]);
            sm += g_psum8[(g * PPB + p) * HH + f];
        }
        g_emb[g * 256 + f] += mx;
        g_emb[g * 256 + 128 + f] += sm * g_inv[g];
    }
}

// ---------------- MLP head ----------------
__global__ void mlp_kernel(const float* __restrict__ W1, const float* __restrict__ b1,
                           const float* __restrict__ W2, const float* __restrict__ b2,
                           const float* __restrict__ W3, const float* __restrict__ b3,
                           float* __restrict__ graphout, float* __restrict__ logits)
{
    __shared__ float in[256];
    __shared__ float z1[128];
    __shared__ float z2[64];
    int g = blockIdx.x;
    int t = threadIdx.x;
    in[t] = g_emb[g * 256 + t];
    in[t + 128] = g_emb[g * 256 + 128 + t];
    graphout[g * 256 + t] = in[t];
    graphout[g * 256 + 128 + t] = in[t + 128];
    __syncthreads();
    {
        float a = b1[t];
        const float* w = &W1[(size_t)t * 256];
#pragma unroll 8
        for (int k = 0; k < 256; k++) a += in[k] * w[k];
        z1[t] = fmaxf(a, 0.f);
    }
    __syncthreads();
    if (t < 64) {
        float a = b2[t];
        const float* w = &W2[(size_t)t * 128];
#pragma unroll 8
        for (int k = 0; k < 128; k++) a += z1[k] * w[k];
        z2[t] = fmaxf(a, 0.f);
    }
    __syncthreads();
    if (t < OO) {
        float a = b3[t];
        const float* w = &W3[(size_t)t * 64];
#pragma unroll
        for (int k = 0; k < 64; k++) a += z2[k] * w[k];
        logits[g * OO + t] = a;
    }
}

// ---------------- launch ----------------
extern "C" void kernel_launch(void* const* d_in, const int* in_sizes, int n_in,
                              void* d_out, int out_size) {
    const float* x   = (const float*)d_in[0];
    const void*  ei  = d_in[1];
    const void*  bat = d_in[2];
    const float* Wr1 = (const float*)d_in[3];
    const float* br1 = (const float*)d_in[4];
    const float* Wo1 = (const float*)d_in[5];
    const float* Wr2 = (const float*)d_in[6];
    const float* br2 = (const float*)d_in[7];
    const float* Wo2 = (const float*)d_in[8];
    const float* Wr3 = (const float*)d_in[9];
    const float* br3 = (const float*)d_in[10];
    const float* Wo3 = (const float*)d_in[11];
    const float* W1  = (const float*)d_in[12];
    const float* b1  = (const float*)d_in[13];
    const float* W2  = (const float*)d_in[14];
    const float* b2  = (const float*)d_in[15];
    const float* W3  = (const float*)d_in[16];
    const float* b3  = (const float*)d_in[17];

    int N = in_sizes[2];          // 50000
    int E = in_sizes[1] / 2;      // 800000

    float* out = (float*)d_out;
    float* logits   = out;
    float* nodeout  = out + GG * OO;
    float* graphout = out + GG * OO + (size_t)N * HH;

    float *bufA, *bufB, *Rp;
    cudaGetSymbolAddress((void**)&bufA, g_bufA);
    cudaGetSymbolAddress((void**)&bufB, g_bufB);
    cudaGetSymbolAddress((void**)&Rp, g_R);
    __nv_bfloat16 *xH, *xL, *aggH, *aggL, *hAH, *hAL, *hBH, *hBL, *wH, *wL;
    cudaGetSymbolAddress((void**)&xH, g_xH);
    cudaGetSymbolAddress((void**)&xL, g_xL);
    cudaGetSymbolAddress((void**)&aggH, g_aggH);
    cudaGetSymbolAddress((void**)&aggL, g_aggL);
    cudaGetSymbolAddress((void**)&hAH, g_hAH);
    cudaGetSymbolAddress((void**)&hAL, g_hAL);
    cudaGetSymbolAddress((void**)&hBH, g_hBH);
    cudaGetSymbolAddress((void**)&hBL, g_hBL);
    cudaGetSymbolAddress((void**)&wH, g_wH);
    cudaGetSymbolAddress((void**)&wL, g_wL);

    static cudaStream_t s2 = nullptr;
    static cudaEvent_t ev[12];
    if (!s2) {
        cudaStreamCreateWithFlags(&s2, cudaStreamNonBlocking);
        for (int i = 0; i < 12; i++)
            cudaEventCreateWithFlags(&ev[i], cudaEventDisableTiming);
        cudaFuncSetAttribute(gemm_half_kernel, cudaFuncAttributeMaxDynamicSharedMemorySize,
                             GEMM_SMEM);
    }

    int nbins = N * SH;
    int scanBlocks = (nbins + SCB - 1) / SCB;   // 782 (<=1024)
    int gemmBlocks = (N + 127) / 128;
    int spmmBlocks = (N + 7) / 8;
    __nv_bfloat16 *WH[6], *WL[6];
    for (int i = 0; i < 6; i++) { WH[i] = wH + i * HH * HH; WL[i] = wL + i * HH * HH; }

    // ---- fork ----
    detect_idx_kernel<<<1, 1>>>(ei, N);
    cudaEventRecord(ev[0], 0);
    cudaStreamWaitEvent(s2, ev[0], 0);

    // side: splits + gemmR1 (R1 = x@Wo1+b1; overlaps CSR build on main), then gstart
    {
        int c4 = (N * HH) / 4;
        split_kernel<<<(c4 + 255) / 256, 256, 0, s2>>>(x, xH, xL, c4);
        split6_kernel<<<(6 * 4096 + 255) / 256, 256, 0, s2>>>(Wr1, Wo1, Wr2, Wo2, Wr3, Wo3,
                                                              wH, wL);
        gemm_half_kernel<<<gemmBlocks, 256, GEMM_SMEM, s2>>>(
            xH, xL, WH[1], WL[1], br1, nullptr, Rp, nullptr, nullptr, N, 0);
        cudaEventRecord(ev[1], s2);  // R1 ready
        gstart_kernel<<<1, 128, 0, s2>>>(bat, N);
    }

    // main: sharded CSR build (spmm1 gathers x directly; no GEMM required first)
    zero_misc_kernel<<<64, 256>>>(nbins);
    hist_edges_kernel<<<(E + 255) / 256, 256>>>(ei, E);
    scan1_kernel<<<scanBlocks, SCB>>>(nbins);
    scan2_kernel<<<1, 1024>>>(scanBlocks, N);
    scan3_kernel<<<scanBlocks, SCB>>>(nbins);
    scatter_kernel<<<(E + 255) / 256, 256>>>(ei, E);

    // ---- layer 1: agg(x) -> rel-GEMM with fused +R1, relu, split out ----
    spmm_split_kernel<<<spmmBlocks, 256>>>(x, aggH, aggL, N);
    cudaStreamWaitEvent(0, ev[1], 0);
    gemm_half_kernel<<<gemmBlocks, 256, GEMM_SMEM>>>(
        aggH, aggL, WH[0], WL[0], nullptr, Rp, bufA, hAH, hAL, N, 1);
    cudaEventRecord(ev[2], 0);  // h1 ready

    // side: gemmR2 (overlaps spmm2 on main) + pool layer 1
    cudaStreamWaitEvent(s2, ev[2], 0);
    gemm_half_kernel<<<gemmBlocks, 256, GEMM_SMEM, s2>>>(
        hAH, hAL, WH[3], WL[3], br2, nullptr, Rp, nullptr, nullptr, N, 0);
    cudaEventRecord(ev[3], s2);  // R2 ready
    pool_kernel<<<GG * PPB, 128, 0, s2>>>(bufA);
    pool_accum_kernel<<<(GG * HH + 255) / 256, 256, 0, s2>>>();

    // ---- layer 2 ----
    spmm_split_kernel<<<spmmBlocks, 256>>>(bufA, aggH, aggL, N);
    cudaStreamWaitEvent(0, ev[3], 0);
    gemm_half_kernel<<<gemmBlocks, 256, GEMM_SMEM>>>(
        aggH, aggL, WH[2], WL[2], nullptr, Rp, bufB, hBH, hBL, N, 1);
    cudaEventRecord(ev[4], 0);  // h2 ready

    // side: gemmR3 (overlaps spmm3) + pool layer 2
    cudaStreamWaitEvent(s2, ev[4], 0);
    gemm_half_kernel<<<gemmBlocks, 256, GEMM_SMEM, s2>>>(
        hBH, hBL, WH[5], WL[5], br3, nullptr, Rp, nullptr, nullptr, N, 0);
    cudaEventRecord(ev[5], s2);  // R3 ready
    pool_kernel<<<GG * PPB, 128, 0, s2>>>(bufB);
    pool_accum_kernel<<<(GG * HH + 255) / 256, 256, 0, s2>>>();

    // ---- layer 3 ----
    spmm_split_kernel<<<spmmBlocks, 256>>>(bufB, aggH, aggL, N);
    cudaStreamWaitEvent(0, ev[5], 0);
    gemm_half_kernel<<<gemmBlocks, 256, GEMM_SMEM>>>(
        aggH, aggL, WH[4], WL[4], nullptr, Rp, nodeout, nullptr, nullptr, N, 1);
    cudaEventRecord(ev[6], 0);  // h3 ready

    // side: pool layer 3
    cudaStreamWaitEvent(s2, ev[6], 0);
    pool_kernel<<<GG * PPB, 128, 0, s2>>>(nodeout);
    pool_accum_kernel<<<(GG * HH + 255) / 256, 256, 0, s2>>>();
    cudaEventRecord(ev[7], s2);

    // final join + head
    cudaStreamWaitEvent(0, ev[7], 0);
    mlp_kernel<<<GG, 128>>>(W1, b1, W2, b2, W3, b3, graphout, logits);
}

// round 15
// speedup vs baseline: 1.0836x; 1.0836x over previous
#include <cuda_runtime.h>
#include <cuda_bf16.h>
#include <cstdint>

// Problem constants (fixed by the dataset)
#define NN 50000
#define EE 800000
#define GG 64
#define HH 128
#define OO 10
#define PPB 8   // pooling partials per graph
#define SCB 256 // scan block size
#define SH  4   // CSR atomic shards per node

// ---------------- static device scratch ----------------
__device__ float g_bufA[NN * HH];
__device__ float g_bufB[NN * HH];
__device__ float g_Y[NN * HH];     // layer-1: x @ W_rel1^T
__device__ float g_R[NN * HH];     // layer-1: x @ W_root1^T + b1
__device__ int   g_count[NN * SH + 1];
__device__ int   g_rowptr[NN + 1];
__device__ int   g_cursor[NN * SH];
__device__ int   g_col[EE];
__device__ int   g_bsum[(NN * SH + SCB - 1) / SCB + 1];
__device__ int   g_boff[(NN * SH + SCB - 1) / SCB + 1];
__device__ int   g_gstart[GG + 1];
__device__ float g_inv[GG];
__device__ float g_pmax8[GG * PPB * HH];
__device__ float g_psum8[GG * PPB * HH];
__device__ float g_emb[GG * 2 * HH];
__device__ int   g_idx64;
// bf16 hi/lo split buffers
__device__ __nv_bfloat16 g_xH[NN * HH],   g_xL[NN * HH];
__device__ __nv_bfloat16 g_aggH[NN * HH], g_aggL[NN * HH];
__device__ __nv_bfloat16 g_hAH[NN * HH],  g_hAL[NN * HH];
__device__ __nv_bfloat16 g_hBH[NN * HH],  g_hBL[NN * HH];
__device__ __nv_bfloat16 g_wH[6 * HH * HH], g_wL[6 * HH * HH];

// ---------------- small helpers ----------------
__device__ __forceinline__ uint32_t pack_bf16(float a, float b) {
    __nv_bfloat162 t = __floats2bfloat162_rn(a, b);
    return *(uint32_t*)&t;
}
__device__ __forceinline__ void ldsm4(uint32_t r[4], const void* p) {
    uint32_t a = (uint32_t)__cvta_generic_to_shared(p);
    asm volatile("ldmatrix.sync.aligned.m8n8.x4.shared.b16 {%0,%1,%2,%3}, [%4];"
                 : "=r"(r[0]), "=r"(r[1]), "=r"(r[2]), "=r"(r[3]) : "r"(a));
}
__device__ __forceinline__ void mma_bf16(float c[4], const uint32_t a[4],
                                         uint32_t b0, uint32_t b1) {
    asm volatile("mma.sync.aligned.m16n8k16.row.col.f32.bf16.bf16.f32 "
                 "{%0,%1,%2,%3}, {%4,%5,%6,%7}, {%8,%9}, {%0,%1,%2,%3};"
                 : "+f"(c[0]), "+f"(c[1]), "+f"(c[2]), "+f"(c[3])
                 : "r"(a[0]), "r"(a[1]), "r"(a[2]), "r"(a[3]), "r"(b0), "r"(b1));
}
// swizzled offset of 16B unit u (0..3) in row r (row = 64B of bf16)
__device__ __forceinline__ int swzoff(int r, int u) {
    return r * 64 + (((u ^ ((r >> 1) & 3)) & 3) << 4);
}
__device__ __forceinline__ void cp_async16(void* dst, const void* src, int bytes) {
    uint32_t d = (uint32_t)__cvta_generic_to_shared(dst);
    asm volatile("cp.async.cg.shared.global [%0], [%1], 16, %2;"
                 :: "r"(d), "l"(src), "r"(bytes) : "memory");
}
#define CP_COMMIT() asm volatile("cp.async.commit_group;" ::: "memory")
#define CP_WAIT1()  asm volatile("cp.async.wait_group 1;" ::: "memory")
#define CP_WAIT0()  asm volatile("cp.async.wait_group 0;" ::: "memory")

// ---------------- index dtype handling ----------------
__device__ __forceinline__ int idx_at(const void* p, long long i) {
    if (g_idx64) return (int)((const long long*)p)[i];
    return ((const int*)p)[i];
}

__global__ void detect_idx_kernel(const void* ei, int n) {
    const long long* p = (const long long*)ei;
    int ok = 1;
    for (int i = 0; i < 4; i++) {
        long long v = p[i];
        if (v < 0 || v >= (long long)n) ok = 0;
    }
    g_idx64 = ok;
}

// ---------------- hi/lo bf16 splits ----------------
__global__ void split_kernel(const float* __restrict__ src, __nv_bfloat16* __restrict__ dh,
                             __nv_bfloat16* __restrict__ dl, int count4) {
    int i = blockIdx.x * blockDim.x + threadIdx.x;
    if (i < count4) {
        float4 v = ((const float4*)src)[i];
        uint32_t h01 = pack_bf16(v.x, v.y);
        uint32_t h23 = pack_bf16(v.z, v.w);
        __nv_bfloat162 h0 = *(__nv_bfloat162*)&h01;
        __nv_bfloat162 h1 = *(__nv_bfloat162*)&h23;
        uint32_t l01 = pack_bf16(v.x - __bfloat162float(h0.x), v.y - __bfloat162float(h0.y));
        uint32_t l23 = pack_bf16(v.z - __bfloat162float(h1.x), v.w - __bfloat162float(h1.y));
        ((uint2*)dh)[i] = make_uint2(h01, h23);
        ((uint2*)dl)[i] = make_uint2(l01, l23);
    }
}

__global__ void split6_kernel(const float* w0, const float* w1, const float* w2,
                              const float* w3, const float* w4, const float* w5,
                              __nv_bfloat16* __restrict__ dh, __nv_bfloat16* __restrict__ dl) {
    int i = blockIdx.x * blockDim.x + threadIdx.x;   // over 6*4096
    if (i < 6 * 4096) {
        int m = i >> 12;
        int j = i & 4095;
        const float* src = (m == 0) ? w0 : (m == 1) ? w1 : (m == 2) ? w2
                          : (m == 3) ? w3 : (m == 4) ? w4 : w5;
        float4 v = ((const float4*)src)[j];
        uint32_t h01 = pack_bf16(v.x, v.y);
        uint32_t h23 = pack_bf16(v.z, v.w);
        __nv_bfloat162 h0 = *(__nv_bfloat162*)&h01;
        __nv_bfloat162 h1 = *(__nv_bfloat162*)&h23;
        uint32_t l01 = pack_bf16(v.x - __bfloat162float(h0.x), v.y - __bfloat162float(h0.y));
        uint32_t l23 = pack_bf16(v.z - __bfloat162float(h1.x), v.w - __bfloat162float(h1.y));
        ((uint2*)dh)[i] = make_uint2(h01, h23);
        ((uint2*)dl)[i] = make_uint2(l01, l23);
    }
}

// ---------------- setup kernels ----------------
__global__ void zero_misc_kernel(int nbins) {
    int stride = gridDim.x * blockDim.x;
    int i = blockIdx.x * blockDim.x + threadIdx.x;
    for (int k = i; k < nbins + 1; k += stride) g_count[k] = 0;
    for (int k = i; k < GG * 2 * HH; k += stride) g_emb[k] = 0.f;
}

__global__ void hist_edges_kernel(const void* ei, int E) {
    int e = blockIdx.x * blockDim.x + threadIdx.x;
    if (e < E) {
        int d = idx_at(ei, (long long)E + e);
        atomicAdd(&g_count[d * SH + (e & (SH - 1))], 1);
    }
}

// ---------------- 3-phase parallel scan over nbins = N*SH ----------------
__global__ void scan1_kernel(int nbins) {
    int i = blockIdx.x * SCB + threadIdx.x;
    int v = (i < nbins) ? g_count[i] : 0;
#pragma unroll
    for (int o = 16; o; o >>= 1) v += __shfl_down_sync(0xffffffffu, v, o);
    __shared__ int ws[SCB / 32];
    if ((threadIdx.x & 31) == 0) ws[threadIdx.x >> 5] = v;
    __syncthreads();
    if (threadIdx.x < SCB / 32) {
        int s = ws[threadIdx.x];
#pragma unroll
        for (int o = (SCB / 64); o; o >>= 1) s += __shfl_down_sync(0xffu, s, o);
        if (threadIdx.x == 0) g_bsum[blockIdx.x] = s;
    }
}

__global__ void scan2_kernel(int nb, int N) {
    int t = threadIdx.x;
    int lane = t & 31;
    int wp = t >> 5;
    int orig = (t < nb) ? g_bsum[t] : 0;
    int v = orig;
#pragma unroll
    for (int o = 1; o < 32; o <<= 1) {
        int u = __shfl_up_sync(0xffffffffu, v, o);
        if (lane >= o) v += u;
    }
    __shared__ int ws[32];
    if (lane == 31) ws[wp] = v;
    __syncthreads();
    if (t < 32) {
        int s = ws[t];
#pragma unroll
        for (int o = 1; o < 32; o <<= 1) {
            int u = __shfl_up_sync(0xffffffffu, s, o);
            if (t >= o) s += u;
        }
        ws[t] = s;
    }
    __syncthreads();
    int incl = v + ((wp > 0) ? ws[wp - 1] : 0);
    if (t < nb) g_boff[t] = incl - orig;
    if (t == nb - 1) g_rowptr[N] = incl;
}

__global__ void scan3_kernel(int nbins) {
    int b = blockIdx.x;
    int t = threadIdx.x;
    int i = b * SCB + t;
    int orig = (i < nbins) ? g_count[i] : 0;
    int v = orig;
#pragma unroll
    for (int o = 1; o < 32; o <<= 1) {
        int u = __shfl_up_sync(0xffffffffu, v, o);
        if ((t & 31) >= o) v += u;
    }
    __shared__ int ws[SCB / 32];
    if ((t & 31) == 31) ws[t >> 5] = v;
    __syncthreads();
    if (t < SCB / 32) {
        int s = ws[t];
#pragma unroll
        for (int o = 1; o < SCB / 32; o <<= 1) {
            int u = __shfl_up_sync((1u << (SCB / 32)) - 1u, s, o);
            if (t >= o) s += u;
        }
        ws[t] = s;
    }
    __syncthreads();
    int incl = v + ((t >= 32) ? ws[(t >> 5) - 1] : 0);
    int excl = incl - orig + g_boff[b];
    if (i < nbins) {
        g_cursor[i] = excl;
        if ((i & (SH - 1)) == 0) g_rowptr[i / SH] = excl;
    }
}

__global__ void scatter_kernel(const void* ei, int E) {
    int e = blockIdx.x * blockDim.x + threadIdx.x;
    if (e < E) {
        int d = idx_at(ei, (long long)E + e);
        int s = idx_at(ei, e);
        int pos = atomicAdd(&g_cursor[d * SH + (e & (SH - 1))], 1);
        g_col[pos] = s;
    }
}

// batch is sorted: graph boundaries via binary search
__global__ void gstart_kernel(const void* batch, int n) {
    int g = threadIdx.x;
    if (g <= GG) {
        if (g == GG) {
            g_gstart[GG] = n;
        } else {
            int lo = 0, hi = n;
            while (lo < hi) {
                int mid = (lo + hi) >> 1;
                if (idx_at(batch, mid) < g) lo = mid + 1; else hi = mid;
            }
            g_gstart[g] = lo;
        }
    }
    __syncthreads();
    if (g < GG) {
        int c = g_gstart[g + 1] - g_gstart[g];
        g_inv[g] = 1.0f / (float)max(c, 1);
    }
}

// ---------------- layer-1 fused SpMM + epilogue ----------------
// h[d] = relu( sum_{e: dst==d} Y[src[e]] + R[d] ); writes fp32 h + bf16 hi/lo splits.
__global__ void __launch_bounds__(256) spmm_fused_kernel(
    const float* __restrict__ Y, const float* __restrict__ R, float* __restrict__ H,
    __nv_bfloat16* __restrict__ Hh, __nv_bfloat16* __restrict__ Hl, int n) {
    int w = (blockIdx.x * blockDim.x + threadIdx.x) >> 5;
    int lane = threadIdx.x & 31;
    if (w >= n) return;
    const float4* h4 = (const float4*)Y;
    int s = g_rowptr[w];
    int e = g_rowptr[w + 1];
    float4 a0 = make_float4(0.f, 0.f, 0.f, 0.f);
    float4 a1 = make_float4(0.f, 0.f, 0.f, 0.f);
    float4 a2 = make_float4(0.f, 0.f, 0.f, 0.f);
    float4 a3 = make_float4(0.f, 0.f, 0.f, 0.f);
    int i = s;
    for (; i + 3 < e; i += 4) {
        int c0 = g_col[i + 0];
        int c1 = g_col[i + 1];
        int c2 = g_col[i + 2];
        int c3 = g_col[i + 3];
        float4 v0 = h4[(size_t)c0 * 32 + lane];
        float4 v1 = h4[(size_t)c1 * 32 + lane];
        float4 v2 = h4[(size_t)c2 * 32 + lane];
        float4 v3 = h4[(size_t)c3 * 32 + lane];
        a0.x += v0.x; a0.y += v0.y; a0.z += v0.z; a0.w += v0.w;
        a1.x += v1.x; a1.y += v1.y; a1.z += v1.z; a1.w += v1.w;
        a2.x += v2.x; a2.y += v2.y; a2.z += v2.z; a2.w += v2.w;
        a3.x += v3.x; a3.y += v3.y; a3.z += v3.z; a3.w += v3.w;
    }
    for (; i < e; i++) {
        float4 v = h4[(size_t)g_col[i] * 32 + lane];
        a0.x += v.x; a0.y += v.y; a0.z += v.z; a0.w += v.w;
    }
    float4 rr = ((const float4*)R)[(size_t)w * 32 + lane];
    float4 o;
    o.x = fmaxf((a0.x + a1.x) + (a2.x + a3.x) + rr.x, 0.f);
    o.y = fmaxf((a0.y + a1.y) + (a2.y + a3.y) + rr.y, 0.f);
    o.z = fmaxf((a0.z + a1.z) + (a2.z + a3.z) + rr.z, 0.f);
    o.w = fmaxf((a0.w + a1.w) + (a2.w + a3.w) + rr.w, 0.f);
    ((float4*)H)[(size_t)w * 32 + lane] = o;
    uint32_t h01 = pack_bf16(o.x, o.y);
    uint32_t h23 = pack_bf16(o.z, o.w);
    __nv_bfloat162 b0 = *(__nv_bfloat162*)&h01;
    __nv_bfloat162 b1 = *(__nv_bfloat162*)&h23;
    uint32_t l01 = pack_bf16(o.x - __bfloat162float(b0.x), o.y - __bfloat162float(b0.y));
    uint32_t l23 = pack_bf16(o.z - __bfloat162float(b1.x), o.w - __bfloat162float(b1.y));
    ((uint2*)Hh)[(size_t)w * 32 + lane] = make_uint2(h01, h23);
    ((uint2*)Hl)[(size_t)w * 32 + lane] = make_uint2(l01, l23);
}

// ---------------- SpMM gather + bf16 split out (layers 2,3) ----------------
__global__ void __launch_bounds__(256) spmm_split_kernel(
    const float* __restrict__ Hsrc, __nv_bfloat16* __restrict__ AggH,
    __nv_bfloat16* __restrict__ AggL, int n) {
    int w = (blockIdx.x * blockDim.x + threadIdx.x) >> 5;
    int lane = threadIdx.x & 31;
    if (w >= n) return;
    const float4* h4 = (const float4*)Hsrc;
    int s = g_rowptr[w];
    int e = g_rowptr[w + 1];
    float4 a0 = make_float4(0.f, 0.f, 0.f, 0.f);
    float4 a1 = make_float4(0.f, 0.f, 0.f, 0.f);
    float4 a2 = make_float4(0.f, 0.f, 0.f, 0.f);
    float4 a3 = make_float4(0.f, 0.f, 0.f, 0.f);
    int i = s;
    for (; i + 3 < e; i += 4) {
        int c0 = g_col[i + 0];
        int c1 = g_col[i + 1];
        int c2 = g_col[i + 2];
        int c3 = g_col[i + 3];
        float4 v0 = h4[(size_t)c0 * 32 + lane];
        float4 v1 = h4[(size_t)c1 * 32 + lane];
        float4 v2 = h4[(size_t)c2 * 32 + lane];
        float4 v3 = h4[(size_t)c3 * 32 + lane];
        a0.x += v0.x; a0.y += v0.y; a0.z += v0.z; a0.w += v0.w;
        a1.x += v1.x; a1.y += v1.y; a1.z += v1.z; a1.w += v1.w;
        a2.x += v2.x; a2.y += v2.y; a2.z += v2.z; a2.w += v2.w;
        a3.x += v3.x; a3.y += v3.y; a3.z += v3.z; a3.w += v3.w;
    }
    for (; i < e; i++) {
        float4 v = h4[(size_t)g_col[i] * 32 + lane];
        a0.x += v.x; a0.y += v.y; a0.z += v.z; a0.w += v.w;
    }
    float4 r;
    r.x = (a0.x + a1.x) + (a2.x + a3.x);
    r.y = (a0.y + a1.y) + (a2.y + a3.y);
    r.z = (a0.z + a1.z) + (a2.z + a3.z);
    r.w = (a0.w + a1.w) + (a2.w + a3.w);
    uint32_t h01 = pack_bf16(r.x, r.y);
    uint32_t h23 = pack_bf16(r.z, r.w);
    __nv_bfloat162 b0 = *(__nv_bfloat162*)&h01;
    __nv_bfloat162 b1 = *(__nv_bfloat162*)&h23;
    uint32_t l01 = pack_bf16(r.x - __bfloat162float(b0.x), r.y - __bfloat162float(b0.y));
    uint32_t l23 = pack_bf16(r.z - __bfloat162float(b1.x), r.w - __bfloat162float(b1.y));
    ((uint2*)AggH)[(size_t)w * 32 + lane] = make_uint2(h01, h23);
    ((uint2*)AggL)[(size_t)w * 32 + lane] = make_uint2(l01, l23);
}

// ---------------- K=128 bf16-split GEMM: C = A@B^T [+bias] ----------------
#define GEMM_SMEM (2 * 4 * 8192)
__global__ void __launch_bounds__(256) gemm_half_kernel(
    const __nv_bfloat16* __restrict__ Ah, const __nv_bfloat16* __restrict__ Al,
    const __nv_bfloat16* __restrict__ Bh, const __nv_bfloat16* __restrict__ Bl,
    const float* __restrict__ bias, float* __restrict__ C, int n)
{
    extern __shared__ __align__(128) uint8_t sm[];
    int tid = threadIdx.x;
    int lane = tid & 31;
    int wid = tid >> 5;
    int warpM = wid & 3;
    int warpN = wid >> 2;
    int row0 = blockIdx.x * 128;

    float acc[2][8][4];
#pragma unroll
    for (int mf = 0; mf < 2; mf++)
#pragma unroll
        for (int nf = 0; nf < 8; nf++)
#pragma unroll
            for (int q = 0; q < 4; q++) acc[mf][nf][q] = 0.f;

    auto load_chunk = [&](int c, int s) {
        int kb2 = c * 64;
        uint8_t* sA_h = sm + s * 32768;
        uint8_t* sA_l = sA_h + 8192;
        uint8_t* sB_h = sA_h + 16384;
        uint8_t* sB_l = sA_h + 24576;
#pragma unroll
        for (int j = 0; j < 2; j++) {
            int uu = tid * 2 + j;
            int row = uu >> 2;
            int un = uu & 3;
            int sw = swzoff(row, un);
            int grow = row0 + row;
            int ok = (grow < n) ? 16 : 0;
            int gr = (grow < n) ? grow : 0;
            size_t aoff = (size_t)gr * 256 + kb2 + un * 16;
            size_t boff = (size_t)row * 256 + kb2 + un * 16;
            cp_async16(sA_h + sw, (const char*)Ah + aoff, ok);
            cp_async16(sA_l + sw, (const char*)Al + aoff, ok);
            cp_async16(sB_h + sw, (const char*)Bh + boff, 16);
            cp_async16(sB_l + sw, (const char*)Bl + boff, 16);
        }
    };

    load_chunk(0, 0);
    CP_COMMIT();

    for (int c = 0; c < 4; c++) {
        int s = c & 1;
        if (c + 1 < 4) {
            load_chunk(c + 1, s ^ 1);
            CP_COMMIT();
            CP_WAIT1();
        } else {
            CP_WAIT0();
        }
        __syncthreads();
        uint8_t* sA_h = sm + s * 32768;
        uint8_t* sA_l = sA_h + 8192;
        uint8_t* sB_h = sA_h + 16384;
        uint8_t* sB_l = sA_h + 24576;
#pragma unroll
        for (int st = 0; st < 2; st++) {
            uint32_t ah[2][4], al[2][4];
            int arow = warpM * 32 + (lane & 15);
            int au = 2 * st + (lane >> 4);
#pragma unroll
            for (int mf = 0; mf < 2; mf++) {
                ldsm4(ah[mf], sA_h + swzoff(arow + mf * 16, au));
                ldsm4(al[mf], sA_l + swzoff(arow + mf * 16, au));
            }
            int brow_off = (lane & 7) + ((lane >> 4) << 3);
            int bu = 2 * st + ((lane >> 3) & 1);
#pragma unroll
            for (int nf2 = 0; nf2 < 4; nf2++) {
                int brow = warpN * 64 + nf2 * 16 + brow_off;
                uint32_t bh[4], bl[4];
                ldsm4(bh, sB_h + swzoff(brow, bu));
                ldsm4(bl, sB_l + swzoff(brow, bu));
#pragma unroll
                for (int half = 0; half < 2; half++) {
                    int nf = nf2 * 2 + half;
#pragma unroll
                    for (int mf = 0; mf < 2; mf++) {
                        mma_bf16(acc[mf][nf], ah[mf], bh[half * 2], bh[half * 2 + 1]);
                        mma_bf16(acc[mf][nf], ah[mf], bl[half * 2], bl[half * 2 + 1]);
                        mma_bf16(acc[mf][nf], al[mf], bh[half * 2], bh[half * 2 + 1]);
                    }
                }
            }
        }
        __syncthreads();
    }
#pragma unroll
    for (int mf = 0; mf < 2; mf++) {
        int row_lo = row0 + warpM * 32 + mf * 16 + (lane >> 2);
#pragma unroll
        for (int nf = 0; nf < 8; nf++) {
            int col = warpN * 64 + nf * 8 + (lane & 3) * 2;
            float b0 = bias ? bias[col] : 0.f;
            float b1 = bias ? bias[col + 1] : 0.f;
#pragma unroll
            for (int hw = 0; hw < 2; hw++) {
                int row = row_lo + hw * 8;
                if (row < n) {
                    float2 o;
                    o.x = acc[mf][nf][hw * 2 + 0] + b0;
                    o.y = acc[mf][nf][hw * 2 + 1] + b1;
                    *(float2*)&C[(size_t)row * 128 + col] = o;
                }
            }
        }
    }
}

// ---------------- K=256 concat GEMM: h' = relu([A0,A1] @ [B0;B1]^T + bias) ----------------
// A0 = agg splits, A1 = h splits (both [N][128] bf16 hi/lo); B0 = W_rel, B1 = W_root.
// 8 k-chunks of 32; chunks 0-3 from (A0,B0), 4-7 from (A1,B1). Writes fp32 + optional splits.
__global__ void __launch_bounds__(256) gemm_cat_kernel(
    const __nv_bfloat16* __restrict__ A0h, const __nv_bfloat16* __restrict__ A0l,
    const __nv_bfloat16* __restrict__ A1h, const __nv_bfloat16* __restrict__ A1l,
    const __nv_bfloat16* __restrict__ B0h, const __nv_bfloat16* __restrict__ B0l,
    const __nv_bfloat16* __restrict__ B1h, const __nv_bfloat16* __restrict__ B1l,
    const float* __restrict__ bias, float* __restrict__ C,
    __nv_bfloat16* __restrict__ Ch, __nv_bfloat16* __restrict__ Cl,
    int n, int writeSplit)
{
    extern __shared__ __align__(128) uint8_t sm[];
    int tid = threadIdx.x;
    int lane = tid & 31;
    int wid = tid >> 5;
    int warpM = wid & 3;
    int warpN = wid >> 2;
    int row0 = blockIdx.x * 128;

    float acc[2][8][4];
#pragma unroll
    for (int mf = 0; mf < 2; mf++)
#pragma unroll
        for (int nf = 0; nf < 8; nf++)
#pragma unroll
            for (int q = 0; q < 4; q++) acc[mf][nf][q] = 0.f;

    auto load_chunk = [&](int c, int s) {
        const __nv_bfloat16* Ah = (c < 4) ? A0h : A1h;
        const __nv_bfloat16* Al = (c < 4) ? A0l : A1l;
        const __nv_bfloat16* Bh = (c < 4) ? B0h : B1h;
        const __nv_bfloat16* Bl = (c < 4) ? B0l : B1l;
        int kb2 = (c & 3) * 64;
        uint8_t* sA_h = sm + s * 32768;
        uint8_t* sA_l = sA_h + 8192;
        uint8_t* sB_h = sA_h + 16384;
        uint8_t* sB_l = sA_h + 24576;
#pragma unroll
        for (int j = 0; j < 2; j++) {
            int uu = tid * 2 + j;
            int row = uu >> 2;
            int un = uu & 3;
            int sw = swzoff(row, un);
            int grow = row0 + row;
            int ok = (grow < n) ? 16 : 0;
            int gr = (grow < n) ? grow : 0;
            size_t aoff = (size_t)gr * 256 + kb2 + un * 16;
            size_t boff = (size_t)row * 256 + kb2 + un * 16;
            cp_async16(sA_h + sw, (const char*)Ah + aoff, ok);
            cp_async16(sA_l + sw, (const char*)Al + aoff, ok);
            cp_async16(sB_h + sw, (const char*)Bh + boff, 16);
            cp_async16(sB_l + sw, (const char*)Bl + boff, 16);
        }
    };

    load_chunk(0, 0);
    CP_COMMIT();

    for (int c = 0; c < 8; c++) {
        int s = c & 1;
        if (c + 1 < 8) {
            load_chunk(c + 1, s ^ 1);
            CP_COMMIT();
            CP_WAIT1();
        } else {
            CP_WAIT0();
        }
        __syncthreads();
        uint8_t* sA_h = sm + s * 32768;
        uint8_t* sA_l = sA_h + 8192;
        uint8_t* sB_h = sA_h + 16384;
        uint8_t* sB_l = sA_h + 24576;
#pragma unroll
        for (int st = 0; st < 2; st++) {
            uint32_t ah[2][4], al[2][4];
            int arow = warpM * 32 + (lane & 15);
            int au = 2 * st + (lane >> 4);
#pragma unroll
            for (int mf = 0; mf < 2; mf++) {
                ldsm4(ah[mf], sA_h + swzoff(arow + mf * 16, au));
                ldsm4(al[mf], sA_l + swzoff(arow + mf * 16, au));
            }
            int brow_off = (lane & 7) + ((lane >> 4) << 3);
            int bu = 2 * st + ((lane >> 3) & 1);
#pragma unroll
            for (int nf2 = 0; nf2 < 4; nf2++) {
                int brow = warpN * 64 + nf2 * 16 + brow_off;
                uint32_t bh[4], bl[4];
                ldsm4(bh, sB_h + swzoff(brow, bu));
                ldsm4(bl, sB_l + swzoff(brow, bu));
#pragma unroll
                for (int half = 0; half < 2; half++) {
                    int nf = nf2 * 2 + half;
#pragma unroll
                    for (int mf = 0; mf < 2; mf++) {
                        mma_bf16(acc[mf][nf], ah[mf], bh[half * 2], bh[half * 2 + 1]);
                        mma_bf16(acc[mf][nf], ah[mf], bl[half * 2], bl[half * 2 + 1]);
                        mma_bf16(acc[mf][nf], al[mf], bh[half * 2], bh[half * 2 + 1]);
                    }
                }
            }
        }
        __syncthreads();
    }
    // ---- epilogue: bias + relu, fp32 out + optional bf16 splits ----
#pragma unroll
    for (int mf = 0; mf < 2; mf++) {
        int row_lo = row0 + warpM * 32 + mf * 16 + (lane >> 2);
#pragma unroll
        for (int nf = 0; nf < 8; nf++) {
            int col = warpN * 64 + nf * 8 + (lane & 3) * 2;
            float b0 = bias[col], b1 = bias[col + 1];
#pragma unroll
            for (int hw = 0; hw < 2; hw++) {
                int row = row_lo + hw * 8;
                if (row < n) {
                    float2 o;
                    o.x = fmaxf(acc[mf][nf][hw * 2 + 0] + b0, 0.f);
                    o.y = fmaxf(acc[mf][nf][hw * 2 + 1] + b1, 0.f);
                    *(float2*)&C[(size_t)row * 128 + col] = o;
                    if (writeSplit) {
                        uint32_t ph = pack_bf16(o.x, o.y);
                        __nv_bfloat162 hb = *(__nv_bfloat162*)&ph;
                        uint32_t pl = pack_bf16(o.x - __bfloat162float(hb.x),
                                                o.y - __bfloat162float(hb.y));
                        ((uint32_t*)Ch)[(size_t)row * 64 + (col >> 1)] = ph;
                        ((uint32_t*)Cl)[(size_t)row * 64 + (col >> 1)] = pl;
                    }
                }
            }
        }
    }
}

// ---------------- pooling ----------------
__global__ void pool_kernel(const float* __restrict__ h) {
    int g = blockIdx.x / PPB;
    int p = blockIdx.x % PPB;
    int t = threadIdx.x;
    int n0 = g_gstart[g];
    int n1 = g_gstart[g + 1];
    int cnt = n1 - n0;
    int chunk = (cnt + PPB - 1) / PPB;
    int i0 = n0 + p * chunk;
    int i1 = min(i0 + chunk, n1);
    float mx0 = 0.f, mx1 = 0.f, sm0 = 0.f, sm1 = 0.f;
    int i = i0;
    for (; i + 1 < i1; i += 2) {
        float v0 = h[(size_t)i * HH + t];
        float v1 = h[(size_t)(i + 1) * HH + t];
        mx0 = fmaxf(mx0, v0);
        mx1 = fmaxf(mx1, v1);
        sm0 += v0;
        sm1 += v1;
    }
    if (i < i1) {
        float v = h[(size_t)i * HH + t];
        mx0 = fmaxf(mx0, v);
        sm0 += v;
    }
    g_pmax8[(g * PPB + p) * HH + t] = fmaxf(mx0, mx1);
    g_psum8[(g * PPB + p) * HH + t] = sm0 + sm1;
}

__global__ void pool_accum_kernel() {
    int idx = blockIdx.x * blockDim.x + threadIdx.x;
    if (idx < GG * HH) {
        int g = idx >> 7;
        int f = idx & 127;
        float mx = 0.f, sm = 0.f;
#pragma unroll
        for (int p = 0; p < PPB; p++) {
            mx = fmaxf(mx, g_pmax8[(g * PPB + p) * HH + f]);
            sm += g_psum8[(g * PPB + p) * HH + f];
        }
        g_emb[g * 256 + f] += mx;
        g_emb[g * 256 + 128 + f] += sm * g_inv[g];
    }
}

// ---------------- MLP head ----------------
__global__ void mlp_kernel(const float* __restrict__ W1, const float* __restrict__ b1,
                           const float* __restrict__ W2, const float* __restrict__ b2,
                           const float* __restrict__ W3, const float* __restrict__ b3,
                           float* __restrict__ graphout, float* __restrict__ logits)
{
    __shared__ float in[256];
    __shared__ float z1[128];
    __shared__ float z2[64];
    int g = blockIdx.x;
    int t = threadIdx.x;
    in[t] = g_emb[g * 256 + t];
    in[t + 128] = g_emb[g * 256 + 128 + t];
    graphout[g * 256 + t] = in[t];
    graphout[g * 256 + 128 + t] = in[t + 128];
    __syncthreads();
    {
        float a = b1[t];
        const float* w = &W1[(size_t)t * 256];
#pragma unroll 8
        for (int k = 0; k < 256; k++) a += in[k] * w[k];
        z1[t] = fmaxf(a, 0.f);
    }
    __syncthreads();
    if (t < 64) {
        float a = b2[t];
        const float* w = &W2[(size_t)t * 128];
#pragma unroll 8
        for (int k = 0; k < 128; k++) a += z1[k] * w[k];
        z2[t] = fmaxf(a, 0.f);
    }
    __syncthreads();
    if (t < OO) {
        float a = b3[t];
        const float* w = &W3[(size_t)t * 64];
#pragma unroll
        for (int k = 0; k < 64; k++) a += z2[k] * w[k];
        logits[g * OO + t] = a;
    }
}

// ---------------- launch ----------------
extern "C" void kernel_launch(void* const* d_in, const int* in_sizes, int n_in,
                              void* d_out, int out_size) {
    const float* x   = (const float*)d_in[0];
    const void*  ei  = d_in[1];
    const void*  bat = d_in[2];
    const float* Wr1 = (const float*)d_in[3];
    const float* br1 = (const float*)d_in[4];
    const float* Wo1 = (const float*)d_in[5];
    const float* Wr2 = (const float*)d_in[6];
    const float* br2 = (const float*)d_in[7];
    const float* Wo2 = (const float*)d_in[8];
    const float* Wr3 = (const float*)d_in[9];
    const float* br3 = (const float*)d_in[10];
    const float* Wo3 = (const float*)d_in[11];
    const float* W1  = (const float*)d_in[12];
    const float* b1  = (const float*)d_in[13];
    const float* W2  = (const float*)d_in[14];
    const float* b2  = (const float*)d_in[15];
    const float* W3  = (const float*)d_in[16];
    const float* b3  = (const float*)d_in[17];

    int N = in_sizes[2];          // 50000
    int E = in_sizes[1] / 2;      // 800000

    float* out = (float*)d_out;
    float* logits   = out;
    float* nodeout  = out + GG * OO;
    float* graphout = out + GG * OO + (size_t)N * HH;

    float *bufA, *bufB, *Yp, *Rp;
    cudaGetSymbolAddress((void**)&bufA, g_bufA);
    cudaGetSymbolAddress((void**)&bufB, g_bufB);
    cudaGetSymbolAddress((void**)&Yp, g_Y);
    cudaGetSymbolAddress((void**)&Rp, g_R);
    __nv_bfloat16 *xH, *xL, *aggH, *aggL, *hAH, *hAL, *hBH, *hBL, *wH, *wL;
    cudaGetSymbolAddress((void**)&xH, g_xH);
    cudaGetSymbolAddress((void**)&xL, g_xL);
    cudaGetSymbolAddress((void**)&aggH, g_aggH);
    cudaGetSymbolAddress((void**)&aggL, g_aggL);
    cudaGetSymbolAddress((void**)&hAH, g_hAH);
    cudaGetSymbolAddress((void**)&hAL, g_hAL);
    cudaGetSymbolAddress((void**)&hBH, g_hBH);
    cudaGetSymbolAddress((void**)&hBL, g_hBL);
    cudaGetSymbolAddress((void**)&wH, g_wH);
    cudaGetSymbolAddress((void**)&wL, g_wL);

    static cudaStream_t s2 = nullptr;
    static cudaEvent_t ev[12];
    if (!s2) {
        cudaStreamCreateWithFlags(&s2, cudaStreamNonBlocking);
        for (int i = 0; i < 12; i++)
            cudaEventCreateWithFlags(&ev[i], cudaEventDisableTiming);
        cudaFuncSetAttribute(gemm_half_kernel, cudaFuncAttributeMaxDynamicSharedMemorySize,
                             GEMM_SMEM);
        cudaFuncSetAttribute(gemm_cat_kernel, cudaFuncAttributeMaxDynamicSharedMemorySize,
                             GEMM_SMEM);
    }

    int nbins = N * SH;
    int scanBlocks = (nbins + SCB - 1) / SCB;   // 782 (<=1024)
    int gemmBlocks = (N + 127) / 128;
    int spmmBlocks = (N + 7) / 8;
    __nv_bfloat16 *WH[6], *WL[6];
    for (int i = 0; i < 6; i++) { WH[i] = wH + i * HH * HH; WL[i] = wL + i * HH * HH; }

    // ---- fork ----
    detect_idx_kernel<<<1, 1>>>(ei, N);
    cudaEventRecord(ev[0], 0);
    cudaStreamWaitEvent(s2, ev[0], 0);

    // side: splits + layer-1 Y/R GEMMs (hide CSR build), then gstart
    {
        int c4 = (N * HH) / 4;
        split_kernel<<<(c4 + 255) / 256, 256, 0, s2>>>(x, xH, xL, c4);
        split6_kernel<<<(6 * 4096 + 255) / 256, 256, 0, s2>>>(Wr1, Wo1, Wr2, Wo2, Wr3, Wo3,
                                                              wH, wL);
        gemm_half_kernel<<<gemmBlocks, 256, GEMM_SMEM, s2>>>(xH, xL, WH[0], WL[0],
                                                             nullptr, Yp, N);
        gemm_half_kernel<<<gemmBlocks, 256, GEMM_SMEM, s2>>>(xH, xL, WH[1], WL[1],
                                                             br1, Rp, N);
        cudaEventRecord(ev[2], s2);  // Y1 + R1 ready
        gstart_kernel<<<1, 128, 0, s2>>>(bat, N);
    }

    // main: sharded CSR build
    zero_misc_kernel<<<64, 256>>>(nbins);
    hist_edges_kernel<<<(E + 255) / 256, 256>>>(ei, E);
    scan1_kernel<<<scanBlocks, SCB>>>(nbins);
    scan2_kernel<<<1, 1024>>>(scanBlocks, N);
    scan3_kernel<<<scanBlocks, SCB>>>(nbins);
    scatter_kernel<<<(E + 255) / 256, 256>>>(ei, E);

    // ---- layer 1 (Y-first): fused spmm+epi -> h1 ----
    cudaStreamWaitEvent(0, ev[2], 0);
    spmm_fused_kernel<<<spmmBlocks, 256>>>(Yp, Rp, bufA, hAH, hAL, N);
    cudaEventRecord(ev[3], 0);  // h1 ready

    // side: pool layer 1
    cudaStreamWaitEvent(s2, ev[3], 0);
    pool_kernel<<<GG * PPB, 128, 0, s2>>>(bufA);
    pool_accum_kernel<<<(GG * HH + 255) / 256, 256, 0, s2>>>();

    // ---- layer 2 (aggregate-first): spmm(h1) -> concat K=256 GEMM ----
    spmm_split_kernel<<<spmmBlocks, 256>>>(bufA, aggH, aggL, N);
    gemm_cat_kernel<<<gemmBlocks, 256, GEMM_SMEM>>>(
        aggH, aggL, hAH, hAL, WH[2], WL[2], WH[3], WL[3], br2, bufB, hBH, hBL, N, 1);
    cudaEventRecord(ev[5], 0);  // h2 ready

    // side: pool layer 2
    cudaStreamWaitEvent(s2, ev[5], 0);
    pool_kernel<<<GG * PPB, 128, 0, s2>>>(bufB);
    pool_accum_kernel<<<(GG * HH + 255) / 256, 256, 0, s2>>>();

    // ---- layer 3 (aggregate-first) ----
    spmm_split_kernel<<<spmmBlocks, 256>>>(bufB, aggH, aggL, N);
    gemm_cat_kernel<<<gemmBlocks, 256, GEMM_SMEM>>>(
        aggH, aggL, hBH, hBL, WH[4], WL[4], WH[5], WL[5], br3, nodeout,
        nullptr, nullptr, N, 0);
    cudaEventRecord(ev[7], 0);  // h3 ready

    // side: pool layer 3
    cudaStreamWaitEvent(s2, ev[7], 0);
    pool_kernel<<<GG * PPB, 128, 0, s2>>>(nodeout);
    pool_accum_kernel<<<(GG * HH + 255) / 256, 256, 0, s2>>>();
    cudaEventRecord(ev[8], s2);

    // final join + head
    cudaStreamWaitEvent(0, ev[8], 0);
    mlp_kernel<<<GG, 128>>>(W1, b1, W2, b2, W3, b3, graphout, logits);
}

// round 16
// speedup vs baseline: 1.1143x; 1.0283x over previous
#include <cuda_runtime.h>
#include <cuda_bf16.h>
#include <cuda_fp16.h>
#include <cstdint>

// Problem constants (fixed by the dataset)
#define NN 50000
#define EE 800000
#define GG 64
#define HH 128
#define OO 10
#define PPB 8   // pooling partials per graph
#define SCB 256 // scan block size
#define SH  4   // CSR atomic shards per node

// ---------------- static device scratch ----------------
__device__ float g_bufA[NN * HH];
__device__ float g_bufB[NN * HH];
__device__ __half g_Y16[NN * HH];  // h @ W_rel^T (fp16 gather operand)
__device__ float g_R[NN * HH];     // h @ W_root^T + b (fp32 skip path)
__device__ int   g_count[NN * SH + 1];
__device__ int   g_rowptr[NN + 1];
__device__ int   g_cursor[NN * SH];
__device__ int   g_col[EE];
__device__ int   g_bsum[(NN * SH + SCB - 1) / SCB + 1];
__device__ int   g_boff[(NN * SH + SCB - 1) / SCB + 1];
__device__ int   g_gstart[GG + 1];
__device__ float g_inv[GG];
__device__ float g_pmax8[GG * PPB * HH];
__device__ float g_psum8[GG * PPB * HH];
__device__ float g_emb[GG * 2 * HH];
__device__ int   g_idx64;
// bf16 hi/lo split buffers (GEMM operands keep full split precision)
__device__ __nv_bfloat16 g_xH[NN * HH],  g_xL[NN * HH];
__device__ __nv_bfloat16 g_hAH[NN * HH], g_hAL[NN * HH];
__device__ __nv_bfloat16 g_hBH[NN * HH], g_hBL[NN * HH];
__device__ __nv_bfloat16 g_wH[6 * HH * HH], g_wL[6 * HH * HH];

// ---------------- small helpers ----------------
__device__ __forceinline__ uint32_t pack_bf16(float a, float b) {
    __nv_bfloat162 t = __floats2bfloat162_rn(a, b);
    return *(uint32_t*)&t;
}
__device__ __forceinline__ void ldsm4(uint32_t r[4], const void* p) {
    uint32_t a = (uint32_t)__cvta_generic_to_shared(p);
    asm volatile("ldmatrix.sync.aligned.m8n8.x4.shared.b16 {%0,%1,%2,%3}, [%4];"
                 : "=r"(r[0]), "=r"(r[1]), "=r"(r[2]), "=r"(r[3]) : "r"(a));
}
__device__ __forceinline__ void mma_bf16(float c[4], const uint32_t a[4],
                                         uint32_t b0, uint32_t b1) {
    asm volatile("mma.sync.aligned.m16n8k16.row.col.f32.bf16.bf16.f32 "
                 "{%0,%1,%2,%3}, {%4,%5,%6,%7}, {%8,%9}, {%0,%1,%2,%3};"
                 : "+f"(c[0]), "+f"(c[1]), "+f"(c[2]), "+f"(c[3])
                 : "r"(a[0]), "r"(a[1]), "r"(a[2]), "r"(a[3]), "r"(b0), "r"(b1));
}
// swizzled offset of 16B unit u (0..3) in row r (row = 64B of bf16)
__device__ __forceinline__ int swzoff(int r, int u) {
    return r * 64 + (((u ^ ((r >> 1) & 3)) & 3) << 4);
}
__device__ __forceinline__ void cp_async16(void* dst, const void* src, int bytes) {
    uint32_t d = (uint32_t)__cvta_generic_to_shared(dst);
    asm volatile("cp.async.cg.shared.global [%0], [%1], 16, %2;"
                 :: "r"(d), "l"(src), "r"(bytes) : "memory");
}
#define CP_COMMIT() asm volatile("cp.async.commit_group;" ::: "memory")
#define CP_WAIT1()  asm volatile("cp.async.wait_group 1;" ::: "memory")
#define CP_WAIT0()  asm volatile("cp.async.wait_group 0;" ::: "memory")

// ---------------- index dtype handling ----------------
__device__ __forceinline__ int idx_at(const void* p, long long i) {
    if (g_idx64) return (int)((const long long*)p)[i];
    return ((const int*)p)[i];
}

__global__ void detect_idx_kernel(const void* ei, int n) {
    const long long* p = (const long long*)ei;
    int ok = 1;
    for (int i = 0; i < 4; i++) {
        long long v = p[i];
        if (v < 0 || v >= (long long)n) ok = 0;
    }
    g_idx64 = ok;
}

// ---------------- hi/lo bf16 splits ----------------
__global__ void split_kernel(const float* __restrict__ src, __nv_bfloat16* __restrict__ dh,
                             __nv_bfloat16* __restrict__ dl, int count4) {
    int i = blockIdx.x * blockDim.x + threadIdx.x;
    if (i < count4) {
        float4 v = ((const float4*)src)[i];
        uint32_t h01 = pack_bf16(v.x, v.y);
        uint32_t h23 = pack_bf16(v.z, v.w);
        __nv_bfloat162 h0 = *(__nv_bfloat162*)&h01;
        __nv_bfloat162 h1 = *(__nv_bfloat162*)&h23;
        uint32_t l01 = pack_bf16(v.x - __bfloat162float(h0.x), v.y - __bfloat162float(h0.y));
        uint32_t l23 = pack_bf16(v.z - __bfloat162float(h1.x), v.w - __bfloat162float(h1.y));
        ((uint2*)dh)[i] = make_uint2(h01, h23);
        ((uint2*)dl)[i] = make_uint2(l01, l23);
    }
}

__global__ void split6_kernel(const float* w0, const float* w1, const float* w2,
                              const float* w3, const float* w4, const float* w5,
                              __nv_bfloat16* __restrict__ dh, __nv_bfloat16* __restrict__ dl) {
    int i = blockIdx.x * blockDim.x + threadIdx.x;   // over 6*4096
    if (i < 6 * 4096) {
        int m = i >> 12;
        int j = i & 4095;
        const float* src = (m == 0) ? w0 : (m == 1) ? w1 : (m == 2) ? w2
                          : (m == 3) ? w3 : (m == 4) ? w4 : w5;
        float4 v = ((const float4*)src)[j];
        uint32_t h01 = pack_bf16(v.x, v.y);
        uint32_t h23 = pack_bf16(v.z, v.w);
        __nv_bfloat162 h0 = *(__nv_bfloat162*)&h01;
        __nv_bfloat162 h1 = *(__nv_bfloat162*)&h23;
        uint32_t l01 = pack_bf16(v.x - __bfloat162float(h0.x), v.y - __bfloat162float(h0.y));
        uint32_t l23 = pack_bf16(v.z - __bfloat162float(h1.x), v.w - __bfloat162float(h1.y));
        ((uint2*)dh)[i] = make_uint2(h01, h23);
        ((uint2*)dl)[i] = make_uint2(l01, l23);
    }
}

// ---------------- setup kernels ----------------
__global__ void zero_misc_kernel(int nbins) {
    int stride = gridDim.x * blockDim.x;
    int i = blockIdx.x * blockDim.x + threadIdx.x;
    for (int k = i; k < nbins + 1; k += stride) g_count[k] = 0;
    for (int k = i; k < GG * 2 * HH; k += stride) g_emb[k] = 0.f;
}

__global__ void hist_edges_kernel(const void* ei, int E) {
    int e = blockIdx.x * blockDim.x + threadIdx.x;
    if (e < E) {
        int d = idx_at(ei, (long long)E + e);
        atomicAdd(&g_count[d * SH + (e & (SH - 1))], 1);
    }
}

// ---------------- 3-phase parallel scan over nbins = N*SH ----------------
__global__ void scan1_kernel(int nbins) {
    int i = blockIdx.x * SCB + threadIdx.x;
    int v = (i < nbins) ? g_count[i] : 0;
#pragma unroll
    for (int o = 16; o; o >>= 1) v += __shfl_down_sync(0xffffffffu, v, o);
    __shared__ int ws[SCB / 32];
    if ((threadIdx.x & 31) == 0) ws[threadIdx.x >> 5] = v;
    __syncthreads();
    if (threadIdx.x < SCB / 32) {
        int s = ws[threadIdx.x];
#pragma unroll
        for (int o = (SCB / 64); o; o >>= 1) s += __shfl_down_sync(0xffu, s, o);
        if (threadIdx.x == 0) g_bsum[blockIdx.x] = s;
    }
}

__global__ void scan2_kernel(int nb, int N) {
    int t = threadIdx.x;
    int lane = t & 31;
    int wp = t >> 5;
    int orig = (t < nb) ? g_bsum[t] : 0;
    int v = orig;
#pragma unroll
    for (int o = 1; o < 32; o <<= 1) {
        int u = __shfl_up_sync(0xffffffffu, v, o);
        if (lane >= o) v += u;
    }
    __shared__ int ws[32];
    if (lane == 31) ws[wp] = v;
    __syncthreads();
    if (t < 32) {
        int s = ws[t];
#pragma unroll
        for (int o = 1; o < 32; o <<= 1) {
            int u = __shfl_up_sync(0xffffffffu, s, o);
            if (t >= o) s += u;
        }
        ws[t] = s;
    }
    __syncthreads();
    int incl = v + ((wp > 0) ? ws[wp - 1] : 0);
    if (t < nb) g_boff[t] = incl - orig;
    if (t == nb - 1) g_rowptr[N] = incl;
}

__global__ void scan3_kernel(int nbins) {
    int b = blockIdx.x;
    int t = threadIdx.x;
    int i = b * SCB + t;
    int orig = (i < nbins) ? g_count[i] : 0;
    int v = orig;
#pragma unroll
    for (int o = 1; o < 32; o <<= 1) {
        int u = __shfl_up_sync(0xffffffffu, v, o);
        if ((t & 31) >= o) v += u;
    }
    __shared__ int ws[SCB / 32];
    if ((t & 31) == 31) ws[t >> 5] = v;
    __syncthreads();
    if (t < SCB / 32) {
        int s = ws[t];
#pragma unroll
        for (int o = 1; o < SCB / 32; o <<= 1) {
            int u = __shfl_up_sync((1u << (SCB / 32)) - 1u, s, o);
            if (t >= o) s += u;
        }
        ws[t] = s;
    }
    __syncthreads();
    int incl = v + ((t >= 32) ? ws[(t >> 5) - 1] : 0);
    int excl = incl - orig + g_boff[b];
    if (i < nbins) {
        g_cursor[i] = excl;
        if ((i & (SH - 1)) == 0) g_rowptr[i / SH] = excl;
    }
}

__global__ void scatter_kernel(const void* ei, int E) {
    int e = blockIdx.x * blockDim.x + threadIdx.x;
    if (e < E) {
        int d = idx_at(ei, (long long)E + e);
        int s = idx_at(ei, e);
        int pos = atomicAdd(&g_cursor[d * SH + (e & (SH - 1))], 1);
        g_col[pos] = s;
    }
}

// batch is sorted: graph boundaries via binary search
__global__ void gstart_kernel(const void* batch, int n) {
    int g = threadIdx.x;
    if (g <= GG) {
        if (g == GG) {
            g_gstart[GG] = n;
        } else {
            int lo = 0, hi = n;
            while (lo < hi) {
                int mid = (lo + hi) >> 1;
                if (idx_at(batch, mid) < g) lo = mid + 1; else hi = mid;
            }
            g_gstart[g] = lo;
        }
    }
    __syncthreads();
    if (g < GG) {
        int c = g_gstart[g + 1] - g_gstart[g];
        g_inv[g] = 1.0f / (float)max(c, 1);
    }
}

// ---------------- fused SpMM (fp16 gather) + epilogue ----------------
// h[d] = relu( sum_{e: dst==d} Y16[src[e]] + R[d] ); fp32 accumulate;
// writes fp32 h + optional bf16 hi/lo splits.
__global__ void __launch_bounds__(256) spmm_fused_f16_kernel(
    const __half* __restrict__ Y, const float* __restrict__ R, float* __restrict__ H,
    __nv_bfloat16* __restrict__ Hh, __nv_bfloat16* __restrict__ Hl,
    int n, int writeSplit) {
    int w = (blockIdx.x * blockDim.x + threadIdx.x) >> 5;
    int lane = threadIdx.x & 31;
    if (w >= n) return;
    const uint2* h2 = (const uint2*)Y;   // 4 halfs per uint2; row = 32 uint2 = 256B
    int s = g_rowptr[w];
    int e = g_rowptr[w + 1];
    float4 a0 = make_float4(0.f, 0.f, 0.f, 0.f);
    float4 a1 = make_float4(0.f, 0.f, 0.f, 0.f);
    float4 a2 = make_float4(0.f, 0.f, 0.f, 0.f);
    float4 a3 = make_float4(0.f, 0.f, 0.f, 0.f);
    int i = s;
    for (; i + 3 < e; i += 4) {
        int c0 = g_col[i + 0];
        int c1 = g_col[i + 1];
        int c2 = g_col[i + 2];
        int c3 = g_col[i + 3];
        uint2 v0 = h2[(size_t)c0 * 32 + lane];
        uint2 v1 = h2[(size_t)c1 * 32 + lane];
        uint2 v2 = h2[(size_t)c2 * 32 + lane];
        uint2 v3 = h2[(size_t)c3 * 32 + lane];
        float2 f0a = __half22float2(*(__half2*)&v0.x), f0b = __half22float2(*(__half2*)&v0.y);
        float2 f1a = __half22float2(*(__half2*)&v1.x), f1b = __half22float2(*(__half2*)&v1.y);
        float2 f2a = __half22float2(*(__half2*)&v2.x), f2b = __half22float2(*(__half2*)&v2.y);
        float2 f3a = __half22float2(*(__half2*)&v3.x), f3b = __half22float2(*(__half2*)&v3.y);
        a0.x += f0a.x; a0.y += f0a.y; a0.z += f0b.x; a0.w += f0b.y;
        a1.x += f1a.x; a1.y += f1a.y; a1.z += f1b.x; a1.w += f1b.y;
        a2.x += f2a.x; a2.y += f2a.y; a2.z += f2b.x; a2.w += f2b.y;
        a3.x += f3a.x; a3.y += f3a.y; a3.z += f3b.x; a3.w += f3b.y;
    }
    for (; i < e; i++) {
        uint2 v = h2[(size_t)g_col[i] * 32 + lane];
        float2 fa = __half22float2(*(__half2*)&v.x), fb = __half22float2(*(__half2*)&v.y);
        a0.x += fa.x; a0.y += fa.y; a0.z += fb.x; a0.w += fb.y;
    }
    float4 rr = ((const float4*)R)[(size_t)w * 32 + lane];
    float4 o;
    o.x = fmaxf((a0.x + a1.x) + (a2.x + a3.x) + rr.x, 0.f);
    o.y = fmaxf((a0.y + a1.y) + (a2.y + a3.y) + rr.y, 0.f);
    o.z = fmaxf((a0.z + a1.z) + (a2.z + a3.z) + rr.z, 0.f);
    o.w = fmaxf((a0.w + a1.w) + (a2.w + a3.w) + rr.w, 0.f);
    ((float4*)H)[(size_t)w * 32 + lane] = o;
    if (writeSplit) {
        uint32_t h01 = pack_bf16(o.x, o.y);
        uint32_t h23 = pack_bf16(o.z, o.w);
        __nv_bfloat162 b0 = *(__nv_bfloat162*)&h01;
        __nv_bfloat162 b1 = *(__nv_bfloat162*)&h23;
        uint32_t l01 = pack_bf16(o.x - __bfloat162float(b0.x), o.y - __bfloat162float(b0.y));
        uint32_t l23 = pack_bf16(o.z - __bfloat162float(b1.x), o.w - __bfloat162float(b1.y));
        ((uint2*)Hh)[(size_t)w * 32 + lane] = make_uint2(h01, h23);
        ((uint2*)Hl)[(size_t)w * 32 + lane] = make_uint2(l01, l23);
    }
}

// ---------------- K=128 bf16-split GEMM: C = A@B^T [+bias] ----------------
// Output: fp32 C (R path) or fp16 C16 (Y path, spmm gather operand).
#define GEMM_SMEM (2 * 4 * 8192)
__global__ void __launch_bounds__(256) gemm_half_kernel(
    const __nv_bfloat16* __restrict__ Ah, const __nv_bfloat16* __restrict__ Al,
    const __nv_bfloat16* __restrict__ Bh, const __nv_bfloat16* __restrict__ Bl,
    const float* __restrict__ bias, float* __restrict__ C, __half* __restrict__ C16,
    int n)
{
    extern __shared__ __align__(128) uint8_t sm[];
    int tid = threadIdx.x;
    int lane = tid & 31;
    int wid = tid >> 5;
    int warpM = wid & 3;
    int warpN = wid >> 2;
    int row0 = blockIdx.x * 128;

    float acc[2][8][4];
#pragma unroll
    for (int mf = 0; mf < 2; mf++)
#pragma unroll
        for (int nf = 0; nf < 8; nf++)
#pragma unroll
            for (int q = 0; q < 4; q++) acc[mf][nf][q] = 0.f;

    auto load_chunk = [&](int c, int s) {
        int kb2 = c * 64;
        uint8_t* sA_h = sm + s * 32768;
        uint8_t* sA_l = sA_h + 8192;
        uint8_t* sB_h = sA_h + 16384;
        uint8_t* sB_l = sA_h + 24576;
#pragma unroll
        for (int j = 0; j < 2; j++) {
            int uu = tid * 2 + j;
            int row = uu >> 2;
            int un = uu & 3;
            int sw = swzoff(row, un);
            int grow = row0 + row;
            int ok = (grow < n) ? 16 : 0;
            int gr = (grow < n) ? grow : 0;
            size_t aoff = (size_t)gr * 256 + kb2 + un * 16;
            size_t boff = (size_t)row * 256 + kb2 + un * 16;
            cp_async16(sA_h + sw, (const char*)Ah + aoff, ok);
            cp_async16(sA_l + sw, (const char*)Al + aoff, ok);
            cp_async16(sB_h + sw, (const char*)Bh + boff, 16);
            cp_async16(sB_l + sw, (const char*)Bl + boff, 16);
        }
    };

    load_chunk(0, 0);
    CP_COMMIT();

    for (int c = 0; c < 4; c++) {
        int s = c & 1;
        if (c + 1 < 4) {
            load_chunk(c + 1, s ^ 1);
            CP_COMMIT();
            CP_WAIT1();
        } else {
            CP_WAIT0();
        }
        __syncthreads();
        uint8_t* sA_h = sm + s * 32768;
        uint8_t* sA_l = sA_h + 8192;
        uint8_t* sB_h = sA_h + 16384;
        uint8_t* sB_l = sA_h + 24576;
#pragma unroll
        for (int st = 0; st < 2; st++) {
            uint32_t ah[2][4], al[2][4];
            int arow = warpM * 32 + (lane & 15);
            int au = 2 * st + (lane >> 4);
#pragma unroll
            for (int mf = 0; mf < 2; mf++) {
                ldsm4(ah[mf], sA_h + swzoff(arow + mf * 16, au));
                ldsm4(al[mf], sA_l + swzoff(arow + mf * 16, au));
            }
            int brow_off = (lane & 7) + ((lane >> 4) << 3);
            int bu = 2 * st + ((lane >> 3) & 1);
#pragma unroll
            for (int nf2 = 0; nf2 < 4; nf2++) {
                int brow = warpN * 64 + nf2 * 16 + brow_off;
                uint32_t bh[4], bl[4];
                ldsm4(bh, sB_h + swzoff(brow, bu));
                ldsm4(bl, sB_l + swzoff(brow, bu));
#pragma unroll
                for (int half = 0; half < 2; half++) {
                    int nf = nf2 * 2 + half;
#pragma unroll
                    for (int mf = 0; mf < 2; mf++) {
                        mma_bf16(acc[mf][nf], ah[mf], bh[half * 2], bh[half * 2 + 1]);
                        mma_bf16(acc[mf][nf], ah[mf], bl[half * 2], bl[half * 2 + 1]);
                        mma_bf16(acc[mf][nf], al[mf], bh[half * 2], bh[half * 2 + 1]);
                    }
                }
            }
        }
        __syncthreads();
    }
#pragma unroll
    for (int mf = 0; mf < 2; mf++) {
        int row_lo = row0 + warpM * 32 + mf * 16 + (lane >> 2);
#pragma unroll
        for (int nf = 0; nf < 8; nf++) {
            int col = warpN * 64 + nf * 8 + (lane & 3) * 2;
            float b0 = bias ? bias[col] : 0.f;
            float b1 = bias ? bias[col + 1] : 0.f;
#pragma unroll
            for (int hw = 0; hw < 2; hw++) {
                int row = row_lo + hw * 8;
                if (row < n) {
                    float ox = acc[mf][nf][hw * 2 + 0] + b0;
                    float oy = acc[mf][nf][hw * 2 + 1] + b1;
                    if (C16) {
                        __half2 hv = __floats2half2_rn(ox, oy);
                        *(__half2*)&C16[(size_t)row * 128 + col] = hv;
                    } else {
                        float2 o = make_float2(ox, oy);
                        *(float2*)&C[(size_t)row * 128 + col] = o;
                    }
                }
            }
        }
    }
}

// ---------------- pooling ----------------
__global__ void pool_kernel(const float* __restrict__ h) {
    int g = blockIdx.x / PPB;
    int p = blockIdx.x % PPB;
    int t = threadIdx.x;
    int n0 = g_gstart[g];
    int n1 = g_gstart[g + 1];
    int cnt = n1 - n0;
    int chunk = (cnt + PPB - 1) / PPB;
    int i0 = n0 + p * chunk;
    int i1 = min(i0 + chunk, n1);
    float mx0 = 0.f, mx1 = 0.f, sm0 = 0.f, sm1 = 0.f;
    int i = i0;
    for (; i + 1 < i1; i += 2) {
        float v0 = h[(size_t)i * HH + t];
        float v1 = h[(size_t)(i + 1) * HH + t];
        mx0 = fmaxf(mx0, v0);
        mx1 = fmaxf(mx1, v1);
        sm0 += v0;
        sm1 += v1;
    }
    if (i < i1) {
        float v = h[(size_t)i * HH + t];
        mx0 = fmaxf(mx0, v);
        sm0 += v;
    }
    g_pmax8[(g * PPB + p) * HH + t] = fmaxf(mx0, mx1);
    g_psum8[(g * PPB + p) * HH + t] = sm0 + sm1;
}

__global__ void pool_accum_kernel() {
    int idx = blockIdx.x * blockDim.x + threadIdx.x;
    if (idx < GG * HH) {
        int g = idx >> 7;
        int f = idx & 127;
        float mx = 0.f, sm = 0.f;
#pragma unroll
        for (int p = 0; p < PPB; p++) {
            mx = fmaxf(mx, g_pmax8[(g * PPB + p) * HH + f]);
            sm += g_psum8[(g * PPB + p) * HH + f];
        }
        g_emb[g * 256 + f] += mx;
        g_emb[g * 256 + 128 + f] += sm * g_inv[g];
    }
}

// ---------------- MLP head ----------------
__global__ void mlp_kernel(const float* __restrict__ W1, const float* __restrict__ b1,
                           const float* __restrict__ W2, const float* __restrict__ b2,
                           const float* __restrict__ W3, const float* __restrict__ b3,
                           float* __restrict__ graphout, float* __restrict__ logits)
{
    __shared__ float in[256];
    __shared__ float z1[128];
    __shared__ float z2[64];
    int g = blockIdx.x;
    int t = threadIdx.x;
    in[t] = g_emb[g * 256 + t];
    in[t + 128] = g_emb[g * 256 + 128 + t];
    graphout[g * 256 + t] = in[t];
    graphout[g * 256 + 128 + t] = in[t + 128];
    __syncthreads();
    {
        float a = b1[t];
        const float* w = &W1[(size_t)t * 256];
#pragma unroll 8
        for (int k = 0; k < 256; k++) a += in[k] * w[k];
        z1[t] = fmaxf(a, 0.f);
    }
    __syncthreads();
    if (t < 64) {
        float a = b2[t];
        const float* w = &W2[(size_t)t * 128];
#pragma unroll 8
        for (int k = 0; k < 128; k++) a += z1[k] * w[k];
        z2[t] = fmaxf(a, 0.f);
    }
    __syncthreads();
    if (t < OO) {
        float a = b3[t];
        const float* w = &W3[(size_t)t * 64];
#pragma unroll
        for (int k = 0; k < 64; k++) a += z2[k] * w[k];
        logits[g * OO + t] = a;
    }
}

// ---------------- launch ----------------
extern "C" void kernel_launch(void* const* d_in, const int* in_sizes, int n_in,
                              void* d_out, int out_size) {
    const float* x   = (const float*)d_in[0];
    const void*  ei  = d_in[1];
    const void*  bat = d_in[2];
    const float* Wr1 = (const float*)d_in[3];
    const float* br1 = (const float*)d_in[4];
    const float* Wo1 = (const float*)d_in[5];
    const float* Wr2 = (const float*)d_in[6];
    const float* br2 = (const float*)d_in[7];
    const float* Wo2 = (const float*)d_in[8];
    const float* Wr3 = (const float*)d_in[9];
    const float* br3 = (const float*)d_in[10];
    const float* Wo3 = (const float*)d_in[11];
    const float* W1  = (const float*)d_in[12];
    const float* b1  = (const float*)d_in[13];
    const float* W2  = (const float*)d_in[14];
    const float* b2  = (const float*)d_in[15];
    const float* W3  = (const float*)d_in[16];
    const float* b3  = (const float*)d_in[17];

    int N = in_sizes[2];          // 50000
    int E = in_sizes[1] / 2;      // 800000

    float* out = (float*)d_out;
    float* logits   = out;
    float* nodeout  = out + GG * OO;
    float* graphout = out + GG * OO + (size_t)N * HH;

    float *bufA, *bufB, *Rp;
    __half* Y16p;
    cudaGetSymbolAddress((void**)&bufA, g_bufA);
    cudaGetSymbolAddress((void**)&bufB, g_bufB);
    cudaGetSymbolAddress((void**)&Y16p, g_Y16);
    cudaGetSymbolAddress((void**)&Rp, g_R);
    __nv_bfloat16 *xH, *xL, *hAH, *hAL, *hBH, *hBL, *wH, *wL;
    cudaGetSymbolAddress((void**)&xH, g_xH);
    cudaGetSymbolAddress((void**)&xL, g_xL);
    cudaGetSymbolAddress((void**)&hAH, g_hAH);
    cudaGetSymbolAddress((void**)&hAL, g_hAL);
    cudaGetSymbolAddress((void**)&hBH, g_hBH);
    cudaGetSymbolAddress((void**)&hBL, g_hBL);
    cudaGetSymbolAddress((void**)&wH, g_wH);
    cudaGetSymbolAddress((void**)&wL, g_wL);

    static cudaStream_t s2 = nullptr;
    static cudaEvent_t ev[12];
    if (!s2) {
        cudaStreamCreateWithFlags(&s2, cudaStreamNonBlocking);
        for (int i = 0; i < 12; i++)
            cudaEventCreateWithFlags(&ev[i], cudaEventDisableTiming);
        cudaFuncSetAttribute(gemm_half_kernel, cudaFuncAttributeMaxDynamicSharedMemorySize,
                             GEMM_SMEM);
    }

    int nbins = N * SH;
    int scanBlocks = (nbins + SCB - 1) / SCB;   // 782 (<=1024)
    int gemmBlocks = (N + 127) / 128;
    int spmmBlocks = (N + 7) / 8;
    __nv_bfloat16 *WH[6], *WL[6];
    for (int i = 0; i < 6; i++) { WH[i] = wH + i * HH * HH; WL[i] = wL + i * HH * HH; }

    // ---- fork ----
    detect_idx_kernel<<<1, 1>>>(ei, N);
    cudaEventRecord(ev[0], 0);
    cudaStreamWaitEvent(s2, ev[0], 0);

    // side: splits + layer-1 GEMMs (hide CSR build), then gstart
    {
        int c4 = (N * HH) / 4;
        split_kernel<<<(c4 + 255) / 256, 256, 0, s2>>>(x, xH, xL, c4);
        split6_kernel<<<(6 * 4096 + 255) / 256, 256, 0, s2>>>(Wr1, Wo1, Wr2, Wo2, Wr3, Wo3,
                                                              wH, wL);
        gemm_half_kernel<<<gemmBlocks, 256, GEMM_SMEM, s2>>>(
            xH, xL, WH[0], WL[0], nullptr, nullptr, Y16p, N);
        gemm_half_kernel<<<gemmBlocks, 256, GEMM_SMEM, s2>>>(
            xH, xL, WH[1], WL[1], br1, Rp, nullptr, N);
        cudaEventRecord(ev[2], s2);  // Y1 + R1 ready
        gstart_kernel<<<1, 128, 0, s2>>>(bat, N);
    }

    // main: sharded CSR build
    zero_misc_kernel<<<64, 256>>>(nbins);
    hist_edges_kernel<<<(E + 255) / 256, 256>>>(ei, E);
    scan1_kernel<<<scanBlocks, SCB>>>(nbins);
    scan2_kernel<<<1, 1024>>>(scanBlocks, N);
    scan3_kernel<<<scanBlocks, SCB>>>(nbins);
    scatter_kernel<<<(E + 255) / 256, 256>>>(ei, E);

    // ---- layer 1: fused spmm(fp16 gather)+epi ----
    cudaStreamWaitEvent(0, ev[2], 0);
    spmm_fused_f16_kernel<<<spmmBlocks, 256>>>(Y16p, Rp, bufA, hAH, hAL, N, 1);
    cudaEventRecord(ev[3], 0);  // h1 ready

    // side: root GEMM layer 2 + pool layer 1
    cudaStreamWaitEvent(s2, ev[3], 0);
    gemm_half_kernel<<<gemmBlocks, 256, GEMM_SMEM, s2>>>(
        hAH, hAL, WH[3], WL[3], br2, Rp, nullptr, N);
    cudaEventRecord(ev[4], s2);  // R2 ready
    pool_kernel<<<GG * PPB, 128, 0, s2>>>(bufA);
    pool_accum_kernel<<<(GG * HH + 255) / 256, 256, 0, s2>>>();

    // ---- layer 2 ----
    gemm_half_kernel<<<gemmBlocks, 256, GEMM_SMEM>>>(
        hAH, hAL, WH[2], WL[2], nullptr, nullptr, Y16p, N);
    cudaStreamWaitEvent(0, ev[4], 0);
    spmm_fused_f16_kernel<<<spmmBlocks, 256>>>(Y16p, Rp, bufB, hBH, hBL, N, 1);
    cudaEventRecord(ev[5], 0);  // h2 ready

    // side: root GEMM layer 3 + pool layer 2
    cudaStreamWaitEvent(s2, ev[5], 0);
    gemm_half_kernel<<<gemmBlocks, 256, GEMM_SMEM, s2>>>(
        hBH, hBL, WH[5], WL[5], br3, Rp, nullptr, N);
    cudaEventRecord(ev[6], s2);  // R3 ready
    pool_kernel<<<GG * PPB, 128, 0, s2>>>(bufB);
    pool_accum_kernel<<<(GG * HH + 255) / 256, 256, 0, s2>>>();

    // ---- layer 3 ----
    gemm_half_kernel<<<gemmBlocks, 256, GEMM_SMEM>>>(
        hBH, hBL, WH[4], WL[4], nullptr, nullptr, Y16p, N);
    cudaStreamWaitEvent(0, ev[6], 0);
    spmm_fused_f16_kernel<<<spmmBlocks, 256>>>(Y16p, Rp, nodeout, nullptr, nullptr, N, 0);
    cudaEventRecord(ev[7], 0);  // h3 ready

    // side: pool layer 3
    cudaStreamWaitEvent(s2, ev[7], 0);
    pool_kernel<<<GG * PPB, 128, 0, s2>>>(nodeout);
    pool_accum_kernel<<<(GG * HH + 255) / 256, 256, 0, s2>>>();
    cudaEventRecord(ev[8], s2);

    // final join + head
    cudaStreamWaitEvent(0, ev[8], 0);
    mlp_kernel<<<GG, 128>>>(W1, b1, W2, b2, W3, b3, graphout, logits);
}

// round 17
// speedup vs baseline: 1.2167x; 1.0919x over previous
#include <cuda_runtime.h>
#include <cuda_bf16.h>
#include <cuda_fp16.h>
#include <cstdint>

// Problem constants (fixed by the dataset)
#define NN 50000
#define EE 800000
#define GG 64
#define HH 128
#define OO 10
#define PPB 8   // pooling partials per graph
#define SCB 256 // scan block size
#define SH  4   // CSR atomic shards per node

// ---------------- static device scratch ----------------
__device__ float g_bufA[NN * HH];
__device__ float g_bufB[NN * HH];
__device__ __half g_Y16[NN * HH];  // h @ W_rel^T (fp16 gather operand)
__device__ float g_R[NN * HH];     // h @ W_root^T + b (fp32 skip path)
__device__ int   g_count[NN * SH + 1];
__device__ int   g_rowptr[NN + 1];
__device__ int   g_cursor[NN * SH];
__device__ int   g_col[EE];
__device__ int   g_bsum[(NN * SH + SCB - 1) / SCB + 1];
__device__ int   g_boff[(NN * SH + SCB - 1) / SCB + 1];
__device__ int   g_gstart[GG + 1];
__device__ float g_inv[GG];
__device__ float g_pmax8[GG * PPB * HH];
__device__ float g_psum8[GG * PPB * HH];
__device__ float g_emb[GG * 2 * HH];
__device__ int   g_idx64;
// bf16 hi/lo split buffers (GEMM operands)
__device__ __nv_bfloat16 g_xH[NN * HH],  g_xL[NN * HH];
__device__ __nv_bfloat16 g_hAH[NN * HH], g_hAL[NN * HH];
__device__ __nv_bfloat16 g_hBH[NN * HH], g_hBL[NN * HH];
__device__ __nv_bfloat16 g_wH[6 * HH * HH], g_wL[6 * HH * HH];

// ---------------- small helpers ----------------
__device__ __forceinline__ uint32_t pack_bf16(float a, float b) {
    __nv_bfloat162 t = __floats2bfloat162_rn(a, b);
    return *(uint32_t*)&t;
}
__device__ __forceinline__ void ldsm4(uint32_t r[4], const void* p) {
    uint32_t a = (uint32_t)__cvta_generic_to_shared(p);
    asm volatile("ldmatrix.sync.aligned.m8n8.x4.shared.b16 {%0,%1,%2,%3}, [%4];"
                 : "=r"(r[0]), "=r"(r[1]), "=r"(r[2]), "=r"(r[3]) : "r"(a));
}
__device__ __forceinline__ void mma_bf16(float c[4], const uint32_t a[4],
                                         uint32_t b0, uint32_t b1) {
    asm volatile("mma.sync.aligned.m16n8k16.row.col.f32.bf16.bf16.f32 "
                 "{%0,%1,%2,%3}, {%4,%5,%6,%7}, {%8,%9}, {%0,%1,%2,%3};"
                 : "+f"(c[0]), "+f"(c[1]), "+f"(c[2]), "+f"(c[3])
                 : "r"(a[0]), "r"(a[1]), "r"(a[2]), "r"(a[3]), "r"(b0), "r"(b1));
}
// swizzled offset of 16B unit u (0..3) in row r (row = 64B of bf16)
__device__ __forceinline__ int swzoff(int r, int u) {
    return r * 64 + (((u ^ ((r >> 1) & 3)) & 3) << 4);
}
__device__ __forceinline__ void cp_async16(void* dst, const void* src, int bytes) {
    uint32_t d = (uint32_t)__cvta_generic_to_shared(dst);
    asm volatile("cp.async.cg.shared.global [%0], [%1], 16, %2;"
                 :: "r"(d), "l"(src), "r"(bytes) : "memory");
}
#define CP_COMMIT() asm volatile("cp.async.commit_group;" ::: "memory")
#define CP_WAIT1()  asm volatile("cp.async.wait_group 1;" ::: "memory")
#define CP_WAIT0()  asm volatile("cp.async.wait_group 0;" ::: "memory")

// ---------------- index dtype handling ----------------
__device__ __forceinline__ int idx_at(const void* p, long long i) {
    if (g_idx64) return (int)((const long long*)p)[i];
    return ((const int*)p)[i];
}

__global__ void detect_idx_kernel(const void* ei, int n) {
    const long long* p = (const long long*)ei;
    int ok = 1;
    for (int i = 0; i < 4; i++) {
        long long v = p[i];
        if (v < 0 || v >= (long long)n) ok = 0;
    }
    g_idx64 = ok;
}

// ---------------- hi/lo bf16 splits ----------------
__global__ void split_kernel(const float* __restrict__ src, __nv_bfloat16* __restrict__ dh,
                             __nv_bfloat16* __restrict__ dl, int count4) {
    int i = blockIdx.x * blockDim.x + threadIdx.x;
    if (i < count4) {
        float4 v = ((const float4*)src)[i];
        uint32_t h01 = pack_bf16(v.x, v.y);
        uint32_t h23 = pack_bf16(v.z, v.w);
        __nv_bfloat162 h0 = *(__nv_bfloat162*)&h01;
        __nv_bfloat162 h1 = *(__nv_bfloat162*)&h23;
        uint32_t l01 = pack_bf16(v.x - __bfloat162float(h0.x), v.y - __bfloat162float(h0.y));
        uint32_t l23 = pack_bf16(v.z - __bfloat162float(h1.x), v.w - __bfloat162float(h1.y));
        ((uint2*)dh)[i] = make_uint2(h01, h23);
        ((uint2*)dl)[i] = make_uint2(l01, l23);
    }
}

__global__ void split6_kernel(const float* w0, const float* w1, const float* w2,
                              const float* w3, const float* w4, const float* w5,
                              __nv_bfloat16* __restrict__ dh, __nv_bfloat16* __restrict__ dl) {
    int i = blockIdx.x * blockDim.x + threadIdx.x;   // over 6*4096
    if (i < 6 * 4096) {
        int m = i >> 12;
        int j = i & 4095;
        const float* src = (m == 0) ? w0 : (m == 1) ? w1 : (m == 2) ? w2
                          : (m == 3) ? w3 : (m == 4) ? w4 : w5;
        float4 v = ((const float4*)src)[j];
        uint32_t h01 = pack_bf16(v.x, v.y);
        uint32_t h23 = pack_bf16(v.z, v.w);
        __nv_bfloat162 h0 = *(__nv_bfloat162*)&h01;
        __nv_bfloat162 h1 = *(__nv_bfloat162*)&h23;
        uint32_t l01 = pack_bf16(v.x - __bfloat162float(h0.x), v.y - __bfloat162float(h0.y));
        uint32_t l23 = pack_bf16(v.z - __bfloat162float(h1.x), v.w - __bfloat162float(h1.y));
        ((uint2*)dh)[i] = make_uint2(h01, h23);
        ((uint2*)dl)[i] = make_uint2(l01, l23);
    }
}

// ---------------- setup kernels ----------------
__global__ void zero_misc_kernel(int nbins) {
    int stride = gridDim.x * blockDim.x;
    int i = blockIdx.x * blockDim.x + threadIdx.x;
    for (int k = i; k < nbins + 1; k += stride) g_count[k] = 0;
    for (int k = i; k < GG * 2 * HH; k += stride) g_emb[k] = 0.f;
}

__global__ void hist_edges_kernel(const void* ei, int E) {
    int e = blockIdx.x * blockDim.x + threadIdx.x;
    if (e < E) {
        int d = idx_at(ei, (long long)E + e);
        atomicAdd(&g_count[d * SH + (e & (SH - 1))], 1);
    }
}

// ---------------- 3-phase parallel scan over nbins = N*SH ----------------
__global__ void scan1_kernel(int nbins) {
    int i = blockIdx.x * SCB + threadIdx.x;
    int v = (i < nbins) ? g_count[i] : 0;
#pragma unroll
    for (int o = 16; o; o >>= 1) v += __shfl_down_sync(0xffffffffu, v, o);
    __shared__ int ws[SCB / 32];
    if ((threadIdx.x & 31) == 0) ws[threadIdx.x >> 5] = v;
    __syncthreads();
    if (threadIdx.x < SCB / 32) {
        int s = ws[threadIdx.x];
#pragma unroll
        for (int o = (SCB / 64); o; o >>= 1) s += __shfl_down_sync(0xffu, s, o);
        if (threadIdx.x == 0) g_bsum[blockIdx.x] = s;
    }
}

__global__ void scan2_kernel(int nb, int N) {
    int t = threadIdx.x;
    int lane = t & 31;
    int wp = t >> 5;
    int orig = (t < nb) ? g_bsum[t] : 0;
    int v = orig;
#pragma unroll
    for (int o = 1; o < 32; o <<= 1) {
        int u = __shfl_up_sync(0xffffffffu, v, o);
        if (lane >= o) v += u;
    }
    __shared__ int ws[32];
    if (lane == 31) ws[wp] = v;
    __syncthreads();
    if (t < 32) {
        int s = ws[t];
#pragma unroll
        for (int o = 1; o < 32; o <<= 1) {
            int u = __shfl_up_sync(0xffffffffu, s, o);
            if (t >= o) s += u;
        }
        ws[t] = s;
    }
    __syncthreads();
    int incl = v + ((wp > 0) ? ws[wp - 1] : 0);
    if (t < nb) g_boff[t] = incl - orig;
    if (t == nb - 1) g_rowptr[N] = incl;
}

__global__ void scan3_kernel(int nbins) {
    int b = blockIdx.x;
    int t = threadIdx.x;
    int i = b * SCB + t;
    int orig = (i < nbins) ? g_count[i] : 0;
    int v = orig;
#pragma unroll
    for (int o = 1; o < 32; o <<= 1) {
        int u = __shfl_up_sync(0xffffffffu, v, o);
        if ((t & 31) >= o) v += u;
    }
    __shared__ int ws[SCB / 32];
    if ((t & 31) == 31) ws[t >> 5] = v;
    __syncthreads();
    if (t < SCB / 32) {
        int s = ws[t];
#pragma unroll
        for (int o = 1; o < SCB / 32; o <<= 1) {
            int u = __shfl_up_sync((1u << (SCB / 32)) - 1u, s, o);
            if (t >= o) s += u;
        }
        ws[t] = s;
    }
    __syncthreads();
    int incl = v + ((t >= 32) ? ws[(t >> 5) - 1] : 0);
    int excl = incl - orig + g_boff[b];
    if (i < nbins) {
        g_cursor[i] = excl;
        if ((i & (SH - 1)) == 0) g_rowptr[i / SH] = excl;
    }
}

__global__ void scatter_kernel(const void* ei, int E) {
    int e = blockIdx.x * blockDim.x + threadIdx.x;
    if (e < E) {
        int d = idx_at(ei, (long long)E + e);
        int s = idx_at(ei, e);
        int pos = atomicAdd(&g_cursor[d * SH + (e & (SH - 1))], 1);
        g_col[pos] = s;
    }
}

// batch is sorted: graph boundaries via binary search
__global__ void gstart_kernel(const void* batch, int n) {
    int g = threadIdx.x;
    if (g <= GG) {
        if (g == GG) {
            g_gstart[GG] = n;
        } else {
            int lo = 0, hi = n;
            while (lo < hi) {
                int mid = (lo + hi) >> 1;
                if (idx_at(batch, mid) < g) lo = mid + 1; else hi = mid;
            }
            g_gstart[g] = lo;
        }
    }
    __syncthreads();
    if (g < GG) {
        int c = g_gstart[g + 1] - g_gstart[g];
        g_inv[g] = 1.0f / (float)max(c, 1);
    }
}

// ---------------- fused SpMM (fp16 gather, unroll-8 MLP) + epilogue ----------------
__global__ void __launch_bounds__(256) spmm_fused_f16_kernel(
    const __half* __restrict__ Y, const float* __restrict__ R, float* __restrict__ H,
    __nv_bfloat16* __restrict__ Hh, __nv_bfloat16* __restrict__ Hl,
    int n, int writeSplit) {
    int w = (blockIdx.x * blockDim.x + threadIdx.x) >> 5;
    int lane = threadIdx.x & 31;
    if (w >= n) return;
    const uint2* h2 = (const uint2*)Y;   // row = 32 uint2 = 256B
    int s = g_rowptr[w];
    int e = g_rowptr[w + 1];
    float4 acc = make_float4(0.f, 0.f, 0.f, 0.f);
    int i = s;
    for (; i + 7 < e; i += 8) {
        // 8 independent col loads, then 8 independent gathers (MLP=8)
        int c[8];
#pragma unroll
        for (int k = 0; k < 8; k++) c[k] = g_col[i + k];
        uint2 v[8];
#pragma unroll
        for (int k = 0; k < 8; k++) v[k] = h2[(size_t)c[k] * 32 + lane];
#pragma unroll
        for (int k = 0; k < 8; k++) {
            float2 fa = __half22float2(*(__half2*)&v[k].x);
            float2 fb = __half22float2(*(__half2*)&v[k].y);
            acc.x += fa.x; acc.y += fa.y; acc.z += fb.x; acc.w += fb.y;
        }
    }
    if (i + 3 < e) {
        int c[4];
#pragma unroll
        for (int k = 0; k < 4; k++) c[k] = g_col[i + k];
        uint2 v[4];
#pragma unroll
        for (int k = 0; k < 4; k++) v[k] = h2[(size_t)c[k] * 32 + lane];
#pragma unroll
        for (int k = 0; k < 4; k++) {
            float2 fa = __half22float2(*(__half2*)&v[k].x);
            float2 fb = __half22float2(*(__half2*)&v[k].y);
            acc.x += fa.x; acc.y += fa.y; acc.z += fb.x; acc.w += fb.y;
        }
        i += 4;
    }
    for (; i < e; i++) {
        uint2 v = h2[(size_t)g_col[i] * 32 + lane];
        float2 fa = __half22float2(*(__half2*)&v.x), fb = __half22float2(*(__half2*)&v.y);
        acc.x += fa.x; acc.y += fa.y; acc.z += fb.x; acc.w += fb.y;
    }
    float4 rr = ((const float4*)R)[(size_t)w * 32 + lane];
    float4 o;
    o.x = fmaxf(acc.x + rr.x, 0.f);
    o.y = fmaxf(acc.y + rr.y, 0.f);
    o.z = fmaxf(acc.z + rr.z, 0.f);
    o.w = fmaxf(acc.w + rr.w, 0.f);
    ((float4*)H)[(size_t)w * 32 + lane] = o;
    if (writeSplit) {
        uint32_t h01 = pack_bf16(o.x, o.y);
        uint32_t h23 = pack_bf16(o.z, o.w);
        __nv_bfloat162 b0 = *(__nv_bfloat162*)&h01;
        __nv_bfloat162 b1 = *(__nv_bfloat162*)&h23;
        uint32_t l01 = pack_bf16(o.x - __bfloat162float(b0.x), o.y - __bfloat162float(b0.y));
        uint32_t l23 = pack_bf16(o.z - __bfloat162float(b1.x), o.w - __bfloat162float(b1.y));
        ((uint2*)Hh)[(size_t)w * 32 + lane] = make_uint2(h01, h23);
        ((uint2*)Hl)[(size_t)w * 32 + lane] = make_uint2(l01, l23);
    }
}

// ---------------- DUAL-output bf16-split GEMM (from R13, verified) ----------------
// One A tile feeds both weight matrices; warpN<2 -> Y (fp16), warpN>=2 -> R (fp32 + bias).
#define GEMM_SMEM_DUAL (2 * 49152)
__global__ void __launch_bounds__(512, 1) gemm_dual_kernel(
    const __nv_bfloat16* __restrict__ Ah, const __nv_bfloat16* __restrict__ Al,
    const __nv_bfloat16* __restrict__ B0h, const __nv_bfloat16* __restrict__ B0l,
    const __nv_bfloat16* __restrict__ B1h, const __nv_bfloat16* __restrict__ B1l,
    const float* __restrict__ bias, __half* __restrict__ Y16, float* __restrict__ R,
    int n)
{
    extern __shared__ __align__(128) uint8_t sm[];
    int tid = threadIdx.x;
    int lane = tid & 31;
    int wid = tid >> 5;
    int warpM = wid & 3;
    int warpN = wid >> 2;
    int row0 = blockIdx.x * 128;

    float acc[2][8][4];
#pragma unroll
    for (int mf = 0; mf < 2; mf++)
#pragma unroll
        for (int nf = 0; nf < 8; nf++)
#pragma unroll
            for (int q = 0; q < 4; q++) acc[mf][nf][q] = 0.f;

    auto load_chunk = [&](int c, int s) {
        int kb2 = c * 64;
        uint8_t* sA_h = sm + s * 49152;
        uint8_t* sA_l = sA_h + 8192;
        uint8_t* sB_h = sA_h + 16384;
        uint8_t* sB_l = sA_h + 32768;
        {
            int row = tid >> 2;
            int un = tid & 3;
            int sw = swzoff(row, un);
            int grow = row0 + row;
            int ok = (grow < n) ? 16 : 0;
            int gr = (grow < n) ? grow : 0;
            size_t aoff = (size_t)gr * 256 + kb2 + un * 16;
            cp_async16(sA_h + sw, (const char*)Ah + aoff, ok);
            cp_async16(sA_l + sw, (const char*)Al + aoff, ok);
        }
#pragma unroll
        for (int j = 0; j < 2; j++) {
            int uu = tid * 2 + j;
            int row = uu >> 2;
            int un = uu & 3;
            int sw = swzoff(row, un);
            const char* bh;
            const char* bl;
            if (row < 128) {
                bh = (const char*)B0h + (size_t)row * 256;
                bl = (const char*)B0l + (size_t)row * 256;
            } else {
                bh = (const char*)B1h + (size_t)(row - 128) * 256;
                bl = (const char*)B1l + (size_t)(row - 128) * 256;
            }
            cp_async16(sB_h + sw, bh + kb2 + un * 16, 16);
            cp_async16(sB_l + sw, bl + kb2 + un * 16, 16);
        }
    };

    load_chunk(0, 0);
    CP_COMMIT();

    for (int c = 0; c < 4; c++) {
        int s = c & 1;
        if (c + 1 < 4) {
            load_chunk(c + 1, s ^ 1);
            CP_COMMIT();
            CP_WAIT1();
        } else {
            CP_WAIT0();
        }
        __syncthreads();
        uint8_t* sA_h = sm + s * 49152;
        uint8_t* sA_l = sA_h + 8192;
        uint8_t* sB_h = sA_h + 16384;
        uint8_t* sB_l = sA_h + 32768;
#pragma unroll
        for (int st = 0; st < 2; st++) {
            uint32_t ah[2][4], al[2][4];
            int arow = warpM * 32 + (lane & 15);
            int au = 2 * st + (lane >> 4);
#pragma unroll
            for (int mf = 0; mf < 2; mf++) {
                ldsm4(ah[mf], sA_h + swzoff(arow + mf * 16, au));
                ldsm4(al[mf], sA_l + swzoff(arow + mf * 16, au));
            }
            int brow_off = (lane & 7) + ((lane >> 4) << 3);
            int bu = 2 * st + ((lane >> 3) & 1);
#pragma unroll
            for (int nf2 = 0; nf2 < 4; nf2++) {
                int brow = warpN * 64 + nf2 * 16 + brow_off;
                uint32_t bh[4], bl[4];
                ldsm4(bh, sB_h + swzoff(brow, bu));
                ldsm4(bl, sB_l + swzoff(brow, bu));
#pragma unroll
                for (int half = 0; half < 2; half++) {
                    int nf = nf2 * 2 + half;
#pragma unroll
                    for (int mf = 0; mf < 2; mf++) {
                        mma_bf16(acc[mf][nf], ah[mf], bh[half * 2], bh[half * 2 + 1]);
                        mma_bf16(acc[mf][nf], ah[mf], bl[half * 2], bl[half * 2 + 1]);
                        mma_bf16(acc[mf][nf], al[mf], bh[half * 2], bh[half * 2 + 1]);
                    }
                }
            }
        }
        __syncthreads();
    }
    // ---- epilogue: Y half -> fp16, R half -> fp32 + bias ----
    int isR = warpN >> 1;
    int coloff = (warpN & 1) * 64;
#pragma unroll
    for (int mf = 0; mf < 2; mf++) {
        int row_lo = row0 + warpM * 32 + mf * 16 + (lane >> 2);
#pragma unroll
        for (int nf = 0; nf < 8; nf++) {
            int col = coloff + nf * 8 + (lane & 3) * 2;
            float b0 = isR ? bias[col] : 0.f;
            float b1 = isR ? bias[col + 1] : 0.f;
#pragma unroll
            for (int hw = 0; hw < 2; hw++) {
                int row = row_lo + hw * 8;
                if (row < n) {
                    float ox = acc[mf][nf][hw * 2 + 0] + b0;
                    float oy = acc[mf][nf][hw * 2 + 1] + b1;
                    if (isR) {
                        *(float2*)&R[(size_t)row * 128 + col] = make_float2(ox, oy);
                    } else {
                        __half2 hv = __floats2half2_rn(ox, oy);
                        *(__half2*)&Y16[(size_t)row * 128 + col] = hv;
                    }
                }
            }
        }
    }
}

// ---------------- pooling ----------------
__global__ void pool_kernel(const float* __restrict__ h) {
    int g = blockIdx.x / PPB;
    int p = blockIdx.x % PPB;
    int t = threadIdx.x;
    int n0 = g_gstart[g];
    int n1 = g_gstart[g + 1];
    int cnt = n1 - n0;
    int chunk = (cnt + PPB - 1) / PPB;
    int i0 = n0 + p * chunk;
    int i1 = min(i0 + chunk, n1);
    float mx0 = 0.f, mx1 = 0.f, sm0 = 0.f, sm1 = 0.f;
    int i = i0;
    for (; i + 1 < i1; i += 2) {
        float v0 = h[(size_t)i * HH + t];
        float v1 = h[(size_t)(i + 1) * HH + t];
        mx0 = fmaxf(mx0, v0);
        mx1 = fmaxf(mx1, v1);
        sm0 += v0;
        sm1 += v1;
    }
    if (i < i1) {
        float v = h[(size_t)i * HH + t];
        mx0 = fmaxf(mx0, v);
        sm0 += v;
    }
    g_pmax8[(g * PPB + p) * HH + t] = fmaxf(mx0, mx1);
    g_psum8[(g * PPB + p) * HH + t] = sm0 + sm1;
}

__global__ void pool_accum_kernel() {
    int idx = blockIdx.x * blockDim.x + threadIdx.x;
    if (idx < GG * HH) {
        int g = idx >> 7;
        int f = idx & 127;
        float mx = 0.f, sm = 0.f;
#pragma unroll
        for (int p = 0; p < PPB; p++) {
            mx = fmaxf(mx, g_pmax8[(g * PPB + p) * HH + f]);
            sm += g_psum8[(g * PPB + p) * HH + f];
        }
        g_emb[g * 256 + f] += mx;
        g_emb[g * 256 + 128 + f] += sm * g_inv[g];
    }
}

// ---------------- MLP head ----------------
__global__ void mlp_kernel(const float* __restrict__ W1, const float* __restrict__ b1,
                           const float* __restrict__ W2, const float* __restrict__ b2,
                           const float* __restrict__ W3, const float* __restrict__ b3,
                           float* __restrict__ graphout, float* __restrict__ logits)
{
    __shared__ float in[256];
    __shared__ float z1[128];
    __shared__ float z2[64];
    int g = blockIdx.x;
    int t = threadIdx.x;
    in[t] = g_emb[g * 256 + t];
    in[t + 128] = g_emb[g * 256 + 128 + t];
    graphout[g * 256 + t] = in[t];
    graphout[g * 256 + 128 + t] = in[t + 128];
    __syncthreads();
    {
        float a = b1[t];
        const float* w = &W1[(size_t)t * 256];
#pragma unroll 8
        for (int k = 0; k < 256; k++) a += in[k] * w[k];
        z1[t] = fmaxf(a, 0.f);
    }
    __syncthreads();
    if (t < 64) {
        float a = b2[t];
        const float* w = &W2[(size_t)t * 128];
#pragma unroll 8
        for (int k = 0; k < 128; k++) a += z1[k] * w[k];
        z2[t] = fmaxf(a, 0.f);
    }
    __syncthreads();
    if (t < OO) {
        float a = b3[t];
        const float* w = &W3[(size_t)t * 64];
#pragma unroll
        for (int k = 0; k < 64; k++) a += z2[k] * w[k];
        logits[g * OO + t] = a;
    }
}

// ---------------- launch ----------------
extern "C" void kernel_launch(void* const* d_in, const int* in_sizes, int n_in,
                              void* d_out, int out_size) {
    const float* x   = (const float*)d_in[0];
    const void*  ei  = d_in[1];
    const void*  bat = d_in[2];
    const float* Wr1 = (const float*)d_in[3];
    const float* br1 = (const float*)d_in[4];
    const float* Wo1 = (const float*)d_in[5];
    const float* Wr2 = (const float*)d_in[6];
    const float* br2 = (const float*)d_in[7];
    const float* Wo2 = (const float*)d_in[8];
    const float* Wr3 = (const float*)d_in[9];
    const float* br3 = (const float*)d_in[10];
    const float* Wo3 = (const float*)d_in[11];
    const float* W1  = (const float*)d_in[12];
    const float* b1  = (const float*)d_in[13];
    const float* W2  = (const float*)d_in[14];
    const float* b2  = (const float*)d_in[15];
    const float* W3  = (const float*)d_in[16];
    const float* b3  = (const float*)d_in[17];

    int N = in_sizes[2];          // 50000
    int E = in_sizes[1] / 2;      // 800000

    float* out = (float*)d_out;
    float* logits   = out;
    float* nodeout  = out + GG * OO;
    float* graphout = out + GG * OO + (size_t)N * HH;

    float *bufA, *bufB, *Rp;
    __half* Y16p;
    cudaGetSymbolAddress((void**)&bufA, g_bufA);
    cudaGetSymbolAddress((void**)&bufB, g_bufB);
    cudaGetSymbolAddress((void**)&Y16p, g_Y16);
    cudaGetSymbolAddress((void**)&Rp, g_R);
    __nv_bfloat16 *xH, *xL, *hAH, *hAL, *hBH, *hBL, *wH, *wL;
    cudaGetSymbolAddress((void**)&xH, g_xH);
    cudaGetSymbolAddress((void**)&xL, g_xL);
    cudaGetSymbolAddress((void**)&hAH, g_hAH);
    cudaGetSymbolAddress((void**)&hAL, g_hAL);
    cudaGetSymbolAddress((void**)&hBH, g_hBH);
    cudaGetSymbolAddress((void**)&hBL, g_hBL);
    cudaGetSymbolAddress((void**)&wH, g_wH);
    cudaGetSymbolAddress((void**)&wL, g_wL);

    static cudaStream_t s2 = nullptr;
    static cudaEvent_t ev[12];
    if (!s2) {
        cudaStreamCreateWithFlags(&s2, cudaStreamNonBlocking);
        for (int i = 0; i < 12; i++)
            cudaEventCreateWithFlags(&ev[i], cudaEventDisableTiming);
        cudaFuncSetAttribute(gemm_dual_kernel, cudaFuncAttributeMaxDynamicSharedMemorySize,
                             GEMM_SMEM_DUAL);
    }

    int nbins = N * SH;
    int scanBlocks = (nbins + SCB - 1) / SCB;   // 782 (<=1024)
    int gemmBlocks = (N + 127) / 128;
    int spmmBlocks = (N + 7) / 8;
    __nv_bfloat16 *WH[6], *WL[6];
    for (int i = 0; i < 6; i++) { WH[i] = wH + i * HH * HH; WL[i] = wL + i * HH * HH; }

    // ---- fork ----
    detect_idx_kernel<<<1, 1>>>(ei, N);
    cudaEventRecord(ev[0], 0);
    cudaStreamWaitEvent(s2, ev[0], 0);

    // side: splits + layer-1 dual GEMM (Y1 fp16 + R1 fp32 in one kernel; hides CSR build)
    {
        int c4 = (N * HH) / 4;
        split_kernel<<<(c4 + 255) / 256, 256, 0, s2>>>(x, xH, xL, c4);
        split6_kernel<<<(6 * 4096 + 255) / 256, 256, 0, s2>>>(Wr1, Wo1, Wr2, Wo2, Wr3, Wo3,
                                                              wH, wL);
        gemm_dual_kernel<<<gemmBlocks, 512, GEMM_SMEM_DUAL, s2>>>(
            xH, xL, WH[0], WL[0], WH[1], WL[1], br1, Y16p, Rp, N);
        cudaEventRecord(ev[2], s2);  // Y1 + R1 ready
        gstart_kernel<<<1, 128, 0, s2>>>(bat, N);
    }

    // main: sharded CSR build
    zero_misc_kernel<<<64, 256>>>(nbins);
    hist_edges_kernel<<<(E + 255) / 256, 256>>>(ei, E);
    scan1_kernel<<<scanBlocks, SCB>>>(nbins);
    scan2_kernel<<<1, 1024>>>(scanBlocks, N);
    scan3_kernel<<<scanBlocks, SCB>>>(nbins);
    scatter_kernel<<<(E + 255) / 256, 256>>>(ei, E);

    // ---- layer 1: fused spmm(fp16 gather)+epi ----
    cudaStreamWaitEvent(0, ev[2], 0);
    spmm_fused_f16_kernel<<<spmmBlocks, 256>>>(Y16p, Rp, bufA, hAH, hAL, N, 1);
    cudaEventRecord(ev[3], 0);  // h1 ready

    // side: pool layer 1
    cudaStreamWaitEvent(s2, ev[3], 0);
    pool_kernel<<<GG * PPB, 128, 0, s2>>>(bufA);
    pool_accum_kernel<<<(GG * HH + 255) / 256, 256, 0, s2>>>();

    // ---- layer 2: dual GEMM + spmm ----
    gemm_dual_kernel<<<gemmBlocks, 512, GEMM_SMEM_DUAL>>>(
        hAH, hAL, WH[2], WL[2], WH[3], WL[3], br2, Y16p, Rp, N);
    spmm_fused_f16_kernel<<<spmmBlocks, 256>>>(Y16p, Rp, bufB, hBH, hBL, N, 1);
    cudaEventRecord(ev[5], 0);  // h2 ready

    // side: pool layer 2
    cudaStreamWaitEvent(s2, ev[5], 0);
    pool_kernel<<<GG * PPB, 128, 0, s2>>>(bufB);
    pool_accum_kernel<<<(GG * HH + 255) / 256, 256, 0, s2>>>();

    // ---- layer 3 ----
    gemm_dual_kernel<<<gemmBlocks, 512, GEMM_SMEM_DUAL>>>(
        hBH, hBL, WH[4], WL[4], WH[5], WL[5], br3, Y16p, Rp, N);
    spmm_fused_f16_kernel<<<spmmBlocks, 256>>>(Y16p, Rp, nodeout, nullptr, nullptr, N, 0);
    cudaEventRecord(ev[7], 0);  // h3 ready

    // side: pool layer 3
    cudaStreamWaitEvent(s2, ev[7], 0);
    pool_kernel<<<GG * PPB, 128, 0, s2>>>(nodeout);
    pool_accum_kernel<<<(GG * HH + 255) / 256, 256, 0, s2>>>();
    cudaEventRecord(ev[8], s2);

    // final join + head
    cudaStreamWaitEvent(0, ev[8], 0);
    mlp_kernel<<<GG, 128>>>(W1, b1, W2, b2, W3, b3, graphout, logits);
}